// round 4
// baseline (speedup 1.0000x reference)
#include <cuda_runtime.h>
#include <math.h>

#define ANG 7
#define CC 32
#define EE 128
#define NHEADS 4
#define NN 224     // feature-group dim (ANG*32)
#define LL 224     // tokens per branch-sample
#define TOKD 7168  // CC*NN
#define HID 85
#define HID2 170
#define BBATCH 4
#define SAMP 896   // BBATCH*NN
#define OUTELEMS 6422528  // 196*32*32*32

// ---------------- scratch (static device, no allocations) ----------------
__device__ float g_At[SAMP * TOKD];            // packed token matrix  [m=(b,l)][f=(c,r)]
__device__ float g_x[BBATCH * EE * LL];        // x after lin          [b][e][l]
__device__ float g_qkvpre[BBATCH * 3 * EE * LL];
__device__ float g_qkv[BBATCH * 3 * EE * LL];
__device__ float g_qn[BBATCH * NHEADS * LL * 32];
__device__ float g_kn[BBATCH * NHEADS * LL * 32];
__device__ float g_vv[BBATCH * NHEADS * LL * 32];
__device__ float g_ao[BBATCH * EE * LL];       // attention output     [b][e][l]
__device__ float g_Xh[SAMP * CC * LL];         // branch-h running x   [s][c][l]
__device__ float g_Xv[SAMP * CC * LL];         // branch-v running x
__device__ float g_h2[SAMP * HID2 * LL];       // FFN hidden
__device__ float g_gate[196 * CC];

// x_lf element for (b,u,v,c,h,w); for a branch, token l and feature r map to (u,h)/(v,w)
__device__ __forceinline__ int gidx(int br, int b, int c, int l, int r) {
    int u, v, h, w;
    if (br == 0) { u = l >> 5; h = l & 31; v = r >> 5; w = r & 31; }
    else         { v = l >> 5; w = l & 31; u = r >> 5; h = r & 31; }
    return (((b * 7 + u) * 7 + v) * CC + c) * 1024 + h * 32 + w;
}

__device__ __forceinline__ float gelu_f(float x) {
    return 0.5f * x * (1.0f + erff(x * 0.70710678118654752440f));
}

// ---------------- K0: pack gathered token matrix ----------------
__global__ void k_pack(const float* __restrict__ xlf, int br) {
    int i = blockIdx.x * blockDim.x + threadIdx.x;   // exact: SAMP*TOKD
    int f = i % TOKD; int m = i / TOKD;
    int b = m / LL, l = m - b * LL;
    int c = f / NN, r = f - c * NN;
    g_At[i] = xlf[gidx(br, b, c, l, r)];
}

// ---------------- K1: lin GEMM  x[b,e,l] = sum_f At[m,f]*lin_w[e,f] ----------------
__global__ void k_lin(const float* __restrict__ lin_w) {
    __shared__ float As[32 * 33], Bs[32 * 33];
    int tid = threadIdx.x;
    int Nx = blockIdx.x, My = blockIdx.y;   // Nx: e-tiles (4), My: m-tiles (28)
    int tn = tid & 31, tg = tid >> 5;
    float acc[4] = {0.f, 0.f, 0.f, 0.f};
    for (int k0 = 0; k0 < TOKD; k0 += 32) {
        #pragma unroll
        for (int q = 0; q < 4; q++) {
            int lin = tid + q * 256;
            int r0 = lin >> 5, c0 = lin & 31;
            As[r0 * 33 + c0] = g_At[(My * 32 + r0) * TOKD + k0 + c0];
            Bs[c0 * 33 + r0] = lin_w[(Nx * 32 + r0) * TOKD + k0 + c0];
        }
        __syncthreads();
        #pragma unroll
        for (int kk = 0; kk < 32; kk++) {
            float bv = Bs[kk * 33 + tn];
            #pragma unroll
            for (int i = 0; i < 4; i++) acc[i] += As[(tg + 8 * i) * 33 + kk] * bv;
        }
        __syncthreads();
    }
    int e = Nx * 32 + tn;
    #pragma unroll
    for (int i = 0; i < 4; i++) {
        int m = My * 32 + tg + 8 * i;
        int b = m / LL, l = m - b * LL;
        g_x[(b * EE + e) * LL + l] = acc[i];
    }
}

// ---------------- K2: LN(E) + qkv 1x1 conv ----------------
__global__ void k_ln_qkv(const float* __restrict__ gw, const float* __restrict__ bw,
                         const float* __restrict__ qkv_w) {
    int p = blockIdx.x; int b = p / LL, l = p - b * LL;
    int tid = threadIdx.x;                   // 128
    __shared__ float s1[128], nv[128];
    float v = g_x[(b * EE + tid) * LL + l];
    s1[tid] = v; __syncthreads();
    for (int s = 64; s > 0; s >>= 1) { if (tid < s) s1[tid] += s1[tid + s]; __syncthreads(); }
    float mean = s1[0] * (1.0f / 128.0f);
    __syncthreads();
    float d = v - mean; s1[tid] = d * d; __syncthreads();
    for (int s = 64; s > 0; s >>= 1) { if (tid < s) s1[tid] += s1[tid + s]; __syncthreads(); }
    float var = s1[0] * (1.0f / 128.0f);
    nv[tid] = d * rsqrtf(var + 1e-6f) * gw[tid] + bw[tid];
    __syncthreads();
    for (int j = tid; j < 384; j += 128) {
        const float4* wr = reinterpret_cast<const float4*>(qkv_w + j * EE);
        float a = 0.f;
        #pragma unroll
        for (int c4 = 0; c4 < 32; c4++) {
            float4 wv = wr[c4];
            a += wv.x * nv[c4 * 4] + wv.y * nv[c4 * 4 + 1] + wv.z * nv[c4 * 4 + 2] + wv.w * nv[c4 * 4 + 3];
        }
        g_qkvpre[(b * 384 + j) * LL + l] = a;
    }
}

// ---------------- K3: depthwise 3x3 on [b,384,7,32] ----------------
__global__ void k_dw3(const float* __restrict__ w) {
    int i = blockIdx.x * blockDim.x + threadIdx.x;  // exact: 4*384*224
    int l = i % LL; int ch = (i / LL) % 384; int b = i / (LL * 384);
    int y = l >> 5, x = l & 31;
    const float* src = g_qkvpre + (b * 384 + ch) * LL;
    float acc = 0.f;
    #pragma unroll
    for (int dy = 0; dy < 3; dy++) {
        int yy = y + dy - 1; if (yy < 0 || yy >= 7) continue;
        #pragma unroll
        for (int dx = 0; dx < 3; dx++) {
            int xx = x + dx - 1; if (xx < 0 || xx >= 32) continue;
            acc += src[yy * 32 + xx] * w[ch * 9 + dy * 3 + dx];
        }
    }
    g_qkv[i] = acc;
}

// ---------------- K4a: l2-normalize q,k; extract v ----------------
__global__ void k_norm() {
    int row = blockIdx.x * 4 + (threadIdx.x >> 5);  // (b*4+h)*224+l, 3584 rows
    int dd = threadIdx.x & 31;
    int l = row % LL; int bh = row / LL; int h = bh & 3; int b = bh >> 2;
    int base = (b * 384 + h * 32 + dd) * LL + l;
    float qv = g_qkv[base];
    float kv = g_qkv[base + 128 * LL];
    float vv = g_qkv[base + 256 * LL];
    float sq = qv * qv, sk = kv * kv;
    #pragma unroll
    for (int o = 16; o > 0; o >>= 1) {
        sq += __shfl_xor_sync(0xffffffffu, sq, o);
        sk += __shfl_xor_sync(0xffffffffu, sk, o);
    }
    float dq = fmaxf(sqrtf(sq), 1e-12f), dk = fmaxf(sqrtf(sk), 1e-12f);
    g_qn[row * 32 + dd] = qv / dq;
    g_kn[row * 32 + dd] = kv / dk;
    g_vv[row * 32 + dd] = vv;
}

// ---------------- K4b: attention, fused per (b,l) ----------------
__global__ void k_attn(const float* __restrict__ temp, const float* __restrict__ attca) {
    int b = blockIdx.x / LL, l = blockIdx.x % LL;
    int tid = threadIdx.x;                   // 256
    __shared__ float sq[128];
    __shared__ float sat[NHEADS * LL];
    __shared__ float red[256];
    if (tid < 128) {
        int h = tid >> 5, dd = tid & 31;
        sq[tid] = g_qn[((b * 4 + h) * LL + l) * 32 + dd];
    }
    __syncthreads();
    int m = tid; bool act = (m < LL);
    float lg[4], p[4];
    if (act) {
        #pragma unroll
        for (int h = 0; h < 4; h++) {
            const float* kr = g_kn + ((b * 4 + h) * LL + m) * 32;
            float s = 0.f;
            #pragma unroll
            for (int d2 = 0; d2 < 32; d2++) s += sq[h * 32 + d2] * kr[d2];
            lg[h] = s * temp[h];
        }
    } else { lg[0] = lg[1] = lg[2] = lg[3] = 0.f; }
    #pragma unroll
    for (int h = 0; h < 4; h++) {
        red[tid] = act ? lg[h] : -1e30f; __syncthreads();
        for (int s = 128; s > 0; s >>= 1) { if (tid < s) red[tid] = fmaxf(red[tid], red[tid + s]); __syncthreads(); }
        float mx = red[0]; __syncthreads();
        float e = act ? expf(lg[h] - mx) : 0.f;
        red[tid] = e; __syncthreads();
        for (int s = 128; s > 0; s >>= 1) { if (tid < s) red[tid] += red[tid + s]; __syncthreads(); }
        p[h] = e / red[0];
        __syncthreads();
    }
    if (act) {
        float ag[4];
        #pragma unroll
        for (int h = 0; h < 4; h++) { float a = fmaxf(lg[h], 0.f); a *= a; ag[h] = gelu_f(a) * a; }
        #pragma unroll
        for (int h = 0; h < 4; h++) {
            float sc = attca[h * 4 + 0] * ag[0] + attca[h * 4 + 1] * ag[1] +
                       attca[h * 4 + 2] * ag[2] + attca[h * 4 + 3] * ag[3];
            float sh = attca[(4 + h) * 4 + 0] * ag[0] + attca[(4 + h) * 4 + 1] * ag[1] +
                       attca[(4 + h) * 4 + 2] * ag[2] + attca[(4 + h) * 4 + 3] * ag[3];
            sat[h * LL + m] = p[h] * (1.0f + sc) + sh;
        }
    }
    __syncthreads();
    if (tid < 128) {
        int h = tid >> 5, dd = tid & 31;
        const float* vb = g_vv + ((b * 4 + h) * LL) * 32 + dd;
        float o = 0.f;
        for (int mm = 0; mm < LL; mm++) o += sat[h * LL + mm] * vb[mm * 32];
        g_ao[(b * EE + h * 32 + dd) * LL + l] = o;
    }
}

// ---------------- K5: proj GEMM + residual, writes X[s][c][l] ----------------
__global__ void k_proj(const float* __restrict__ xlf, const float* __restrict__ proj_w, int br) {
    __shared__ float As[32 * 33], Bs[32 * 33];
    int tid = threadIdx.x;
    int t0 = blockIdx.x * 32, l0 = blockIdx.y * 32, b = blockIdx.z;
    int tl = tid & 31, tg = tid >> 5;
    float acc[4] = {0.f, 0.f, 0.f, 0.f};
    #pragma unroll
    for (int k0 = 0; k0 < 128; k0 += 32) {
        #pragma unroll
        for (int q = 0; q < 4; q++) {
            int lin = tid + q * 256;
            int r0 = lin >> 5, c0 = lin & 31;
            As[r0 * 33 + c0] = proj_w[(t0 + r0) * EE + k0 + c0];
            Bs[r0 * 33 + c0] = g_ao[(b * EE + k0 + r0) * LL + l0 + c0];
        }
        __syncthreads();
        #pragma unroll
        for (int kk = 0; kk < 32; kk++) {
            float bv = Bs[kk * 33 + tl];
            #pragma unroll
            for (int i = 0; i < 4; i++) acc[i] += As[(tg + 8 * i) * 33 + kk] * bv;
        }
        __syncthreads();
    }
    float* X = br ? g_Xv : g_Xh;
    int l = l0 + tl;
    #pragma unroll
    for (int i = 0; i < 4; i++) {
        int t = t0 + tg + 8 * i;
        int c = t / NN, r = t - c * NN;
        X[((b * NN + r) * CC + c) * LL + l] = acc[i] + xlf[gidx(br, b, c, l, r)];
    }
}

// ---------------- K6: LN(C) + pin 1x1 -> hidden ----------------
__global__ void k_ffn1(const float* __restrict__ lg_, const float* __restrict__ lb_,
                       const float* __restrict__ pin_w, int br) {
    int s = blockIdx.x;
    int l = threadIdx.x;                     // 224
    __shared__ float spin[HID2 * 32];
    const float* X = br ? g_Xv : g_Xh;
    for (int i = l; i < HID2 * 32; i += 224) spin[i] = pin_w[i];
    float xv[32];
    const float* xr = X + s * CC * LL + l;
    float mean = 0.f;
    #pragma unroll
    for (int c = 0; c < 32; c++) { xv[c] = xr[c * LL]; mean += xv[c]; }
    mean *= (1.0f / 32.0f);
    float var = 0.f;
    #pragma unroll
    for (int c = 0; c < 32; c++) { float d = xv[c] - mean; xv[c] = d; var += d * d; }
    var *= (1.0f / 32.0f);
    float rs = rsqrtf(var + 1e-6f);
    #pragma unroll
    for (int c = 0; c < 32; c++) xv[c] = xv[c] * rs * lg_[c] + lb_[c];
    __syncthreads();
    float* outr = g_h2 + s * HID2 * LL + l;
    for (int j = 0; j < HID2; j++) {
        const float4* p4 = reinterpret_cast<const float4*>(spin + j * 32);
        float a = 0.f;
        #pragma unroll
        for (int q = 0; q < 8; q++) {
            float4 w4 = p4[q];
            a += w4.x * xv[q * 4] + w4.y * xv[q * 4 + 1] + w4.z * xv[q * 4 + 2] + w4.w * xv[q * 4 + 3];
        }
        outr[j * LL] = a;
    }
}

// ---------------- K7: dw3 + gelu-gate + pout + residual (in place on X) ----------------
__global__ void k_ffn2(const float* __restrict__ dw_w, const float* __restrict__ pout_w, int br) {
    int s = blockIdx.x;
    int tid = threadIdx.x;                   // 224
    __shared__ float st[2 * LL];
    __shared__ float spoT[HID * 32];         // [j][c]
    __shared__ float sdw[HID2 * 9];
    for (int i = tid; i < HID * 32; i += 224) {
        int c = i & 31, j = i >> 5;
        spoT[i] = pout_w[c * HID + j];
    }
    for (int i = tid; i < HID2 * 9; i += 224) sdw[i] = dw_w[i];
    int y = tid >> 5, x = tid & 31;
    float acc[32];
    #pragma unroll
    for (int c = 0; c < 32; c++) acc[c] = 0.f;
    const float* h2s = g_h2 + s * HID2 * LL;
    for (int j = 0; j < HID; j++) {
        __syncthreads();
        st[tid]      = h2s[j * LL + tid];
        st[LL + tid] = h2s[(HID + j) * LL + tid];
        __syncthreads();
        float a = 0.f, g2 = 0.f;
        #pragma unroll
        for (int dy = 0; dy < 3; dy++) {
            int yy = y + dy - 1; if (yy < 0 || yy >= 7) continue;
            #pragma unroll
            for (int dx = 0; dx < 3; dx++) {
                int xx = x + dx - 1; if (xx < 0 || xx >= 32) continue;
                int li = yy * 32 + xx;
                a  += st[li] * sdw[j * 9 + dy * 3 + dx];
                g2 += st[LL + li] * sdw[(HID + j) * 9 + dy * 3 + dx];
            }
        }
        float gj = gelu_f(a) * g2;
        const float4* p4 = reinterpret_cast<const float4*>(spoT + j * 32);
        #pragma unroll
        for (int q = 0; q < 8; q++) {
            float4 w4 = p4[q];
            acc[q * 4]     += w4.x * gj;
            acc[q * 4 + 1] += w4.y * gj;
            acc[q * 4 + 2] += w4.z * gj;
            acc[q * 4 + 3] += w4.w * gj;
        }
    }
    float* X = (br ? g_Xv : g_Xh) + s * CC * LL + tid;
    #pragma unroll
    for (int c = 0; c < 32; c++) X[c * LL] += acc[c];
}

// ---------------- K8a: global max pool + gate MLP ----------------
__global__ void k_gate(const float* __restrict__ f1, const float* __restrict__ f2) {
    int t = blockIdx.x;                       // 196
    int b = t / 49; int uv = t - b * 49; int u = uv / 7; int v = uv - u * 7;
    int tid = threadIdx.x;                    // 256
    int c2 = tid & 63, part = tid >> 6;
    __shared__ float red[256], mx[64], sg1[8];
    bool is2 = c2 >= 32; int c = is2 ? c2 - 32 : c2;
    float m = -1e30f;
    for (int j = 0; j < 256; j++) {
        int hw = part * 256 + j;
        int h = hw >> 5, w = hw & 31;
        float val;
        if (!is2) val = g_Xh[((b * NN + v * 32 + w) * CC + c) * LL + u * 32 + h];
        else      val = g_Xv[((b * NN + u * 32 + h) * CC + c) * LL + v * 32 + w];
        m = fmaxf(m, val);
    }
    red[tid] = m; __syncthreads();
    if (tid < 64) mx[tid] = fmaxf(fmaxf(red[tid], red[tid + 64]), fmaxf(red[tid + 128], red[tid + 192]));
    __syncthreads();
    if (tid < 8) {
        float a = 0.f;
        for (int k = 0; k < 64; k++) a += f1[tid * 64 + k] * mx[k];
        sg1[tid] = (a >= 0.f) ? a : 0.1f * a;
    }
    __syncthreads();
    if (tid < 32) {
        float a = 0.f;
        #pragma unroll
        for (int i = 0; i < 8; i++) a += f2[tid * 8 + i] * sg1[i];
        g_gate[t * 32 + tid] = 1.0f / (1.0f + expf(-a));
    }
}

// ---------------- K8b: gated mix to output layout ----------------
__global__ void k_final(float* __restrict__ out) {
    int i = blockIdx.x * blockDim.x + threadIdx.x;  // exact: OUTELEMS
    int w = i & 31; int h = (i >> 5) & 31; int c = (i >> 10) & 31; int t = i >> 15;
    int b = t / 49; int uv = t - b * 49; int u = uv / 7; int v = uv - u * 7;
    float o1 = g_Xh[((b * NN + v * 32 + w) * CC + c) * LL + u * 32 + h];
    float o2 = g_Xv[((b * NN + u * 32 + h) * CC + c) * LL + v * 32 + w];
    float gt = g_gate[t * 32 + c];
    out[i] = o1 * gt + o2 * (1.0f - gt);
}

// ---------------- launch ----------------
extern "C" void kernel_launch(void* const* d_in, const int* in_sizes, int n_in,
                              void* d_out, int out_size) {
    (void)in_sizes; (void)n_in; (void)out_size;
    const float* xlf = (const float*)d_in[0];
    const float* f1  = (const float*)d_in[27];
    const float* f2  = (const float*)d_in[28];
    for (int br = 0; br < 2; br++) {
        int o = 1 + br * 13;
        const float* lin_w  = (const float*)d_in[o + 0];
        const float* temp   = (const float*)d_in[o + 1];
        const float* ln1_g  = (const float*)d_in[o + 2];
        const float* ln1_b  = (const float*)d_in[o + 3];
        const float* qkv_w  = (const float*)d_in[o + 4];
        const float* qkvdw  = (const float*)d_in[o + 5];
        const float* proj_w = (const float*)d_in[o + 6];
        const float* attca  = (const float*)d_in[o + 7];
        const float* lne_g  = (const float*)d_in[o + 8];
        const float* lne_b  = (const float*)d_in[o + 9];
        const float* pin_w  = (const float*)d_in[o + 10];
        const float* dw_w   = (const float*)d_in[o + 11];
        const float* pout_w = (const float*)d_in[o + 12];

        k_pack  <<<SAMP * TOKD / 256, 256>>>(xlf, br);
        k_lin   <<<dim3(4, 28), 256>>>(lin_w);
        k_ln_qkv<<<896, 128>>>(ln1_g, ln1_b, qkv_w);
        k_dw3   <<<(BBATCH * 384 * LL) / 256, 256>>>(qkvdw);
        k_norm  <<<896, 128>>>();
        k_attn  <<<896, 256>>>(temp, attca);
        k_proj  <<<dim3(224, 7, 4), 256>>>(xlf, proj_w, br);
        k_ffn1  <<<896, 224>>>(lne_g, lne_b, pin_w, br);
        k_ffn2  <<<896, 224>>>(dw_w, pout_w, br);
    }
    k_gate <<<196, 256>>>(f1, f2);
    k_final<<<OUTELEMS / 256, 256>>>((float*)d_out);
}

// round 11
// speedup vs baseline: 2.1175x; 2.1175x over previous
#include <cuda_runtime.h>
#include <math.h>

#define ANG 7
#define CC 32
#define EE 128
#define NHEADS 4
#define NN 224
#define LL 224
#define TOKD 7168
#define HID 85
#define HID2 170
#define BBATCH 4
#define SAMP 896
#define KSPLIT 16
#define KCH 448          // TOKD / KSPLIT
#define OUTELEMS 6422528

// ---------------- scratch (16B-aligned: accessed via float4) ----------------
__device__ __align__(16) float g_At[SAMP * TOKD];              // [m=(b,l)][f=(c,r)]
__device__ __align__(16) float g_R[SAMP * CC * LL];            // residual, X layout [s][c][l]
__device__ __align__(16) float g_xpart[KSPLIT * SAMP * EE];    // lin partials [kb][m][e]
__device__ __align__(16) float g_qkvpre[BBATCH * 3 * EE * LL];
__device__ __align__(16) float g_qkv[BBATCH * 3 * EE * LL];
__device__ __align__(16) float g_qn[BBATCH * NHEADS * LL * 32];
__device__ __align__(16) float g_kn[BBATCH * NHEADS * LL * 32];
__device__ __align__(16) float g_vv[BBATCH * NHEADS * LL * 32];
__device__ __align__(16) float g_ao[BBATCH * EE * LL];         // [b][e][l]
__device__ __align__(16) float g_Xh[SAMP * CC * LL];
__device__ __align__(16) float g_Xv[SAMP * CC * LL];
__device__ __align__(16) float g_gate[196 * CC];

__device__ __forceinline__ float gelu_f(float x) {
    return 0.5f * x * (1.0f + erff(x * 0.70710678118654752440f));
}

// ---------------- K0: pack (tile transpose) -> g_At and g_R ----------------
__global__ void k_pack(const float* __restrict__ xlf, int br) {
    // block per (t=(b,u,v), c); 32x32 tile (h,w); sm[h][w]
    int bid = blockIdx.x;
    int c = bid & 31; int t = bid >> 5;
    int b = t / 49; int uv = t - b * 49; int u = uv / 7; int v = uv - u * 7;
    __shared__ float sm[32][33];
    int tid = threadIdx.x;
    int lane = tid & 31, row = tid >> 5;
    const float* src = xlf + ((size_t)t * 32 + c) * 1024;
    #pragma unroll
    for (int p = 0; p < 4; p++) {
        int h = row + p * 8;
        sm[h][lane] = src[h * 32 + lane];
    }
    __syncthreads();
    if (br == 0) {
        #pragma unroll
        for (int p = 0; p < 4; p++) {
            int h = row + p * 8;   // direct: l=u*32+h, r=v*32+w(lane); value x(h, w=lane)
            g_At[(b * 224 + u * 32 + h) * TOKD + c * 224 + v * 32 + lane] = sm[h][lane];
            int w = row + p * 8;   // transposed: n=v*32+w, l=u*32+lane; value x(h=lane, w)
            g_R[((b * NN + v * 32 + w) * CC + c) * LL + u * 32 + lane] = sm[lane][w];
        }
    } else {
        #pragma unroll
        for (int p = 0; p < 4; p++) {
            int w = row + p * 8;   // transposed: l=v*32+w, r=u*32+lane; value x(h=lane, w)
            g_At[(b * 224 + v * 32 + w) * TOKD + c * 224 + u * 32 + lane] = sm[lane][w];
            int h = row + p * 8;   // direct: n=u*32+h, l=v*32+lane; value x(h, w=lane)
            g_R[((b * NN + u * 32 + h) * CC + c) * LL + v * 32 + lane] = sm[h][lane];
        }
    }
}

// ---------------- K1: lin GEMM, split-K, 64x64 tiles, 16 acc/thread ----------------
__global__ void k_lin(const float* __restrict__ lin_w) {
    // grid (2 e-tiles, 14 m-tiles, 16 kb), 256 threads
    __shared__ __align__(16) float As[16 * 68];  // [k][m]
    __shared__ __align__(16) float Bs[16 * 68];  // [k][e]
    int tid = threadIdx.x;
    int tx = tid & 15, ty = tid >> 4;
    int e0 = blockIdx.x * 64, m0 = blockIdx.y * 64, kb = blockIdx.z;
    int kbase = kb * KCH;
    float acc[4][4];
    #pragma unroll
    for (int i = 0; i < 4; i++)
        #pragma unroll
        for (int j = 0; j < 4; j++) acc[i][j] = 0.f;
    int r = tid >> 2, q = tid & 3;
    for (int ks = 0; ks < KCH; ks += 16) {
        float4 av = *(const float4*)&g_At[(m0 + r) * TOKD + kbase + ks + q * 4];
        float4 bv = *(const float4*)&lin_w[(e0 + r) * TOKD + kbase + ks + q * 4];
        As[(q * 4 + 0) * 68 + r] = av.x; As[(q * 4 + 1) * 68 + r] = av.y;
        As[(q * 4 + 2) * 68 + r] = av.z; As[(q * 4 + 3) * 68 + r] = av.w;
        Bs[(q * 4 + 0) * 68 + r] = bv.x; Bs[(q * 4 + 1) * 68 + r] = bv.y;
        Bs[(q * 4 + 2) * 68 + r] = bv.z; Bs[(q * 4 + 3) * 68 + r] = bv.w;
        __syncthreads();
        #pragma unroll
        for (int kk = 0; kk < 16; kk++) {
            float4 a = *(const float4*)&As[kk * 68 + ty * 4];
            float4 b2 = *(const float4*)&Bs[kk * 68 + tx * 4];
            acc[0][0] += a.x * b2.x; acc[0][1] += a.x * b2.y; acc[0][2] += a.x * b2.z; acc[0][3] += a.x * b2.w;
            acc[1][0] += a.y * b2.x; acc[1][1] += a.y * b2.y; acc[1][2] += a.y * b2.z; acc[1][3] += a.y * b2.w;
            acc[2][0] += a.z * b2.x; acc[2][1] += a.z * b2.y; acc[2][2] += a.z * b2.z; acc[2][3] += a.z * b2.w;
            acc[3][0] += a.w * b2.x; acc[3][1] += a.w * b2.y; acc[3][2] += a.w * b2.z; acc[3][3] += a.w * b2.w;
        }
        __syncthreads();
    }
    #pragma unroll
    for (int i = 0; i < 4; i++) {
        int m = m0 + ty * 4 + i;
        float4 st4 = make_float4(acc[i][0], acc[i][1], acc[i][2], acc[i][3]);
        *(float4*)&g_xpart[(kb * SAMP + m) * EE + e0 + tx * 4] = st4;
    }
}

// ---------------- K2: reduce partials + LN(E) + qkv 1x1 ----------------
__global__ void k_ln_qkv(const float* __restrict__ gw, const float* __restrict__ bw,
                         const float* __restrict__ qkv_w) {
    int p = blockIdx.x; int b = p / LL, l = p - b * LL;
    int tid = threadIdx.x;  // 128
    __shared__ __align__(16) float s1[128];
    __shared__ __align__(16) float nv[128];
    float v = 0.f;
    #pragma unroll
    for (int kb = 0; kb < KSPLIT; kb++) v += g_xpart[(kb * SAMP + p) * EE + tid];
    s1[tid] = v; __syncthreads();
    for (int s = 64; s > 0; s >>= 1) { if (tid < s) s1[tid] += s1[tid + s]; __syncthreads(); }
    float mean = s1[0] * (1.0f / 128.0f);
    __syncthreads();
    float d = v - mean; s1[tid] = d * d; __syncthreads();
    for (int s = 64; s > 0; s >>= 1) { if (tid < s) s1[tid] += s1[tid + s]; __syncthreads(); }
    float var = s1[0] * (1.0f / 128.0f);
    nv[tid] = d * rsqrtf(var + 1e-6f) * gw[tid] + bw[tid];
    __syncthreads();
    for (int j = tid; j < 384; j += 128) {
        const float4* wr = reinterpret_cast<const float4*>(qkv_w + j * EE);
        float a = 0.f;
        #pragma unroll
        for (int c4 = 0; c4 < 32; c4++) {
            float4 wv = wr[c4];
            a += wv.x * nv[c4 * 4] + wv.y * nv[c4 * 4 + 1] + wv.z * nv[c4 * 4 + 2] + wv.w * nv[c4 * 4 + 3];
        }
        g_qkvpre[(b * 384 + j) * LL + l] = a;
    }
}

// ---------------- K3: depthwise 3x3 ----------------
__global__ void k_dw3(const float* __restrict__ w) {
    int i = blockIdx.x * blockDim.x + threadIdx.x;
    int l = i % LL; int ch = (i / LL) % 384; int b = i / (LL * 384);
    int y = l >> 5, x = l & 31;
    const float* src = g_qkvpre + (b * 384 + ch) * LL;
    float acc = 0.f;
    #pragma unroll
    for (int dy = 0; dy < 3; dy++) {
        int yy = y + dy - 1; if (yy < 0 || yy >= 7) continue;
        #pragma unroll
        for (int dx = 0; dx < 3; dx++) {
            int xx = x + dx - 1; if (xx < 0 || xx >= 32) continue;
            acc += src[yy * 32 + xx] * w[ch * 9 + dy * 3 + dx];
        }
    }
    g_qkv[i] = acc;
}

// ---------------- K4a: l2-normalize q,k ----------------
__global__ void k_norm() {
    int row = blockIdx.x * 4 + (threadIdx.x >> 5);
    int dd = threadIdx.x & 31;
    int l = row % LL; int bh = row / LL; int h = bh & 3; int b = bh >> 2;
    int base = (b * 384 + h * 32 + dd) * LL + l;
    float qv = g_qkv[base];
    float kv = g_qkv[base + 128 * LL];
    float vv = g_qkv[base + 256 * LL];
    float sq = qv * qv, sk = kv * kv;
    #pragma unroll
    for (int o = 16; o > 0; o >>= 1) {
        sq += __shfl_xor_sync(0xffffffffu, sq, o);
        sk += __shfl_xor_sync(0xffffffffu, sk, o);
    }
    float dq = fmaxf(sqrtf(sq), 1e-12f), dk = fmaxf(sqrtf(sk), 1e-12f);
    g_qn[row * 32 + dd] = qv / dq;
    g_kn[row * 32 + dd] = kv / dk;
    g_vv[row * 32 + dd] = vv;
}

// ---------------- K4b: attention, 4 tokens per block ----------------
__global__ void k_attn(const float* __restrict__ temp, const float* __restrict__ attca) {
    int tg0 = blockIdx.x * 4;
    int b = blockIdx.y;
    int tid = threadIdx.x;  // 256
    __shared__ __align__(16) float sq[4 * 128];
    __shared__ __align__(16) float sat[16 * 224];
    __shared__ __align__(16) float outp[256 * 4];
    __shared__ float wred[8 * 16];
    __shared__ float gred[16];
    __shared__ float sca[32];
    if (tid < 32) sca[tid] = attca[tid];
    for (int i = tid; i < 512; i += 256) {
        int t = i >> 7, hd = i & 127;
        sq[i] = g_qn[((b * 4 + (hd >> 5)) * LL + tg0 + t) * 32 + (hd & 31)];
    }
    __syncthreads();

    int m = tid; bool act = (m < LL);
    float lg[16];
    if (act) {
        #pragma unroll
        for (int h = 0; h < 4; h++) {
            const float4* kr = (const float4*)&g_kn[((b * 4 + h) * LL + m) * 32];
            float s[4] = {0.f, 0.f, 0.f, 0.f};
            #pragma unroll
            for (int q = 0; q < 8; q++) {
                float4 kv = kr[q];
                #pragma unroll
                for (int t = 0; t < 4; t++) {
                    float4 qv = *(const float4*)&sq[t * 128 + h * 32 + q * 4];
                    s[t] += kv.x * qv.x + kv.y * qv.y + kv.z * qv.z + kv.w * qv.w;
                }
            }
            float tp = temp[h];
            #pragma unroll
            for (int t = 0; t < 4; t++) lg[h * 4 + t] = s[t] * tp;
        }
    } else {
        #pragma unroll
        for (int i = 0; i < 16; i++) lg[i] = -1e30f;
    }
    int wid = tid >> 5, lane = tid & 31;
    // max reduce
    float red[16];
    #pragma unroll
    for (int i = 0; i < 16; i++) red[i] = lg[i];
    #pragma unroll
    for (int o = 16; o > 0; o >>= 1) {
        #pragma unroll
        for (int i = 0; i < 16; i++) red[i] = fmaxf(red[i], __shfl_xor_sync(0xffffffffu, red[i], o));
    }
    if (lane == 0) {
        #pragma unroll
        for (int i = 0; i < 16; i++) wred[wid * 16 + i] = red[i];
    }
    __syncthreads();
    if (tid < 16) {
        float vmx = wred[tid];
        #pragma unroll
        for (int w = 1; w < 8; w++) vmx = fmaxf(vmx, wred[w * 16 + tid]);
        gred[tid] = vmx;
    }
    __syncthreads();
    float e[16];
    #pragma unroll
    for (int i = 0; i < 16; i++) e[i] = act ? expf(lg[i] - gred[i]) : 0.f;
    __syncthreads();
    // sum reduce
    #pragma unroll
    for (int i = 0; i < 16; i++) red[i] = e[i];
    #pragma unroll
    for (int o = 16; o > 0; o >>= 1) {
        #pragma unroll
        for (int i = 0; i < 16; i++) red[i] += __shfl_xor_sync(0xffffffffu, red[i], o);
    }
    if (lane == 0) {
        #pragma unroll
        for (int i = 0; i < 16; i++) wred[wid * 16 + i] = red[i];
    }
    __syncthreads();
    if (tid < 16) {
        float vs = wred[tid];
        #pragma unroll
        for (int w = 1; w < 8; w++) vs += wred[w * 16 + tid];
        gred[tid] = vs;
    }
    __syncthreads();
    if (act) {
        float ag[16];
        #pragma unroll
        for (int i = 0; i < 16; i++) { float a = fmaxf(lg[i], 0.f); a *= a; ag[i] = gelu_f(a) * a; }
        #pragma unroll
        for (int t = 0; t < 4; t++) {
            #pragma unroll
            for (int h = 0; h < 4; h++) {
                float sc = sca[h * 4 + 0] * ag[0 * 4 + t] + sca[h * 4 + 1] * ag[1 * 4 + t] +
                           sca[h * 4 + 2] * ag[2 * 4 + t] + sca[h * 4 + 3] * ag[3 * 4 + t];
                float sh = sca[(4 + h) * 4 + 0] * ag[0 * 4 + t] + sca[(4 + h) * 4 + 1] * ag[1 * 4 + t] +
                           sca[(4 + h) * 4 + 2] * ag[2 * 4 + t] + sca[(4 + h) * 4 + 3] * ag[3 * 4 + t];
                float p = e[h * 4 + t] / gred[h * 4 + t];
                sat[(t * 4 + h) * 224 + m] = p * (1.0f + sc) + sh;
            }
        }
    }
    __syncthreads();
    // AV: all 256 threads; two mm-halves
    {
        int half = tid >> 7, hd = tid & 127, h = hd >> 5, dd = hd & 31;
        float o[4] = {0.f, 0.f, 0.f, 0.f};
        const float* vb = &g_vv[((b * 4 + h) * LL) * 32 + dd];
        int mmend = half * 112 + 112;
        for (int mm = half * 112; mm < mmend; mm++) {
            float v = vb[mm * 32];
            #pragma unroll
            for (int t = 0; t < 4; t++) o[t] += sat[(t * 4 + h) * 224 + mm] * v;
        }
        #pragma unroll
        for (int t = 0; t < 4; t++) outp[tid * 4 + t] = o[t];
    }
    __syncthreads();
    if (tid < 128) {
        float4 r4;
        r4.x = outp[tid * 4 + 0] + outp[(tid + 128) * 4 + 0];
        r4.y = outp[tid * 4 + 1] + outp[(tid + 128) * 4 + 1];
        r4.z = outp[tid * 4 + 2] + outp[(tid + 128) * 4 + 2];
        r4.w = outp[tid * 4 + 3] + outp[(tid + 128) * 4 + 3];
        *(float4*)&g_ao[(b * EE + tid) * LL + tg0] = r4;
    }
}

// ---------------- K5: proj GEMM + residual (coalesced via g_R) ----------------
__global__ void k_proj(const float* __restrict__ proj_w, int br) {
    // grid (112 t-tiles, 7 l-tiles, 4 b), 128 threads; tile 64t x 32l
    __shared__ __align__(16) float As[16 * 68];  // [k][t]
    __shared__ __align__(16) float Bs[16 * 36];  // [k][l]
    int tid = threadIdx.x;
    int tx = tid & 7, ty = tid >> 3;  // tx: l quad (8x4), ty: t quad (16x4)
    int t0 = blockIdx.x * 64, l0 = blockIdx.y * 32, b = blockIdx.z;
    float acc[4][4];
    #pragma unroll
    for (int i = 0; i < 4; i++)
        #pragma unroll
        for (int j = 0; j < 4; j++) acc[i][j] = 0.f;
    for (int ks = 0; ks < EE; ks += 16) {
        #pragma unroll
        for (int ii = 0; ii < 2; ii++) {
            int idx = tid * 2 + ii;
            int r = idx >> 2, q = idx & 3;
            float4 a4 = *(const float4*)&proj_w[(t0 + r) * EE + ks + q * 4];
            As[(q * 4 + 0) * 68 + r] = a4.x; As[(q * 4 + 1) * 68 + r] = a4.y;
            As[(q * 4 + 2) * 68 + r] = a4.z; As[(q * 4 + 3) * 68 + r] = a4.w;
        }
        {
            int r = tid >> 3, q = tid & 7;
            float4 b4 = *(const float4*)&g_ao[(b * EE + ks + r) * LL + l0 + q * 4];
            *(float4*)&Bs[r * 36 + q * 4] = b4;
        }
        __syncthreads();
        #pragma unroll
        for (int kk = 0; kk < 16; kk++) {
            float4 a = *(const float4*)&As[kk * 68 + ty * 4];
            float4 b2 = *(const float4*)&Bs[kk * 36 + tx * 4];
            acc[0][0] += a.x * b2.x; acc[0][1] += a.x * b2.y; acc[0][2] += a.x * b2.z; acc[0][3] += a.x * b2.w;
            acc[1][0] += a.y * b2.x; acc[1][1] += a.y * b2.y; acc[1][2] += a.y * b2.z; acc[1][3] += a.y * b2.w;
            acc[2][0] += a.z * b2.x; acc[2][1] += a.z * b2.y; acc[2][2] += a.z * b2.z; acc[2][3] += a.z * b2.w;
            acc[3][0] += a.w * b2.x; acc[3][1] += a.w * b2.y; acc[3][2] += a.w * b2.z; acc[3][3] += a.w * b2.w;
        }
        __syncthreads();
    }
    float* X = br ? g_Xv : g_Xh;
    #pragma unroll
    for (int i = 0; i < 4; i++) {
        int t = t0 + ty * 4 + i;
        int c = t / NN, r = t - c * NN;
        int base = ((b * NN + r) * CC + c) * LL + l0 + tx * 4;
        float4 res = *(const float4*)&g_R[base];
        float4 o;
        o.x = acc[i][0] + res.x; o.y = acc[i][1] + res.y;
        o.z = acc[i][2] + res.z; o.w = acc[i][3] + res.w;
        *(float4*)&X[base] = o;
    }
}

// ---------------- K6: fused FFN (LN + pin + dw3 + gelu-gate + pout + residual) ----------------
__global__ void k_ffn(const float* __restrict__ lg_, const float* __restrict__ lb_,
                      const float* __restrict__ pin_w, const float* __restrict__ dw_w,
                      const float* __restrict__ pout_w, int br) {
    int s = blockIdx.x;
    int l = threadIdx.x;  // 224
    __shared__ __align__(16) float spin[HID2 * 32];
    __shared__ __align__(16) float spoT[HID * 32];
    __shared__ __align__(16) float st[2 * LL];
    __shared__ float sdw[HID2 * 9];     // scalar-only access; declared last
    for (int i = l; i < HID2 * 32; i += 224) spin[i] = pin_w[i];
    for (int i = l; i < HID2 * 9; i += 224) sdw[i] = dw_w[i];
    for (int i = l; i < HID * 32; i += 224) {
        int c = i & 31, j = i >> 5;
        spoT[i] = pout_w[c * HID + j];
    }
    float* X = (br ? g_Xv : g_Xh) + s * CC * LL + l;
    float xv[32];
    float mean = 0.f;
    #pragma unroll
    for (int c = 0; c < 32; c++) { xv[c] = X[c * LL]; mean += xv[c]; }
    mean *= (1.0f / 32.0f);
    float var = 0.f;
    #pragma unroll
    for (int c = 0; c < 32; c++) { float d = xv[c] - mean; xv[c] = d; var += d * d; }
    var *= (1.0f / 32.0f);
    float rs = rsqrtf(var + 1e-6f);
    #pragma unroll
    for (int c = 0; c < 32; c++) xv[c] = xv[c] * rs * lg_[c] + lb_[c];
    __syncthreads();
    float acc[32];
    #pragma unroll
    for (int c = 0; c < 32; c++) acc[c] = 0.f;
    int y = l >> 5, x = l & 31;
    for (int j = 0; j < HID; j++) {
        const float4* p1 = (const float4*)&spin[j * 32];
        const float4* p2 = (const float4*)&spin[(HID + j) * 32];
        float a = 0.f, g2 = 0.f;
        #pragma unroll
        for (int q = 0; q < 8; q++) {
            float4 w1 = p1[q]; float4 w2 = p2[q];
            a  += w1.x * xv[q * 4] + w1.y * xv[q * 4 + 1] + w1.z * xv[q * 4 + 2] + w1.w * xv[q * 4 + 3];
            g2 += w2.x * xv[q * 4] + w2.y * xv[q * 4 + 1] + w2.z * xv[q * 4 + 2] + w2.w * xv[q * 4 + 3];
        }
        st[l] = a; st[LL + l] = g2;
        __syncthreads();
        float ca = 0.f, cg = 0.f;
        #pragma unroll
        for (int dy = 0; dy < 3; dy++) {
            int yy = y + dy - 1; if (yy < 0 || yy >= 7) continue;
            #pragma unroll
            for (int dx = 0; dx < 3; dx++) {
                int xx = x + dx - 1; if (xx < 0 || xx >= 32) continue;
                int li = yy * 32 + xx;
                ca += st[li] * sdw[j * 9 + dy * 3 + dx];
                cg += st[LL + li] * sdw[(HID + j) * 9 + dy * 3 + dx];
            }
        }
        float gj = gelu_f(ca) * cg;
        const float4* p4 = (const float4*)&spoT[j * 32];
        #pragma unroll
        for (int q = 0; q < 8; q++) {
            float4 w4 = p4[q];
            acc[q * 4]     += w4.x * gj;
            acc[q * 4 + 1] += w4.y * gj;
            acc[q * 4 + 2] += w4.z * gj;
            acc[q * 4 + 3] += w4.w * gj;
        }
        __syncthreads();
    }
    #pragma unroll
    for (int c = 0; c < 32; c++) X[c * LL] += acc[c];
}

// ---------------- K7: gate (coalesced max pool + MLP) ----------------
__global__ void k_gate(const float* __restrict__ f1, const float* __restrict__ f2) {
    int t = blockIdx.x;
    int b = t / 49; int uv = t - b * 49; int u = uv / 7; int v = uv - u * 7;
    int tid = threadIdx.x;  // 256
    int wid = tid >> 5, lane = tid & 31;
    __shared__ float mx[64], sg1[8];
    #pragma unroll
    for (int k = 0; k < 8; k++) {
        int combo = wid * 8 + k;
        int c = combo & 31; bool is2 = combo >= 32;
        float m = -1e30f;
        if (!is2) {
            for (int w = 0; w < 32; w++)
                m = fmaxf(m, g_Xh[((b * NN + v * 32 + w) * CC + c) * LL + u * 32 + lane]);
        } else {
            for (int h = 0; h < 32; h++)
                m = fmaxf(m, g_Xv[((b * NN + u * 32 + h) * CC + c) * LL + v * 32 + lane]);
        }
        #pragma unroll
        for (int o = 16; o > 0; o >>= 1) m = fmaxf(m, __shfl_xor_sync(0xffffffffu, m, o));
        if (lane == 0) mx[combo] = m;
    }
    __syncthreads();
    if (tid < 8) {
        float a = 0.f;
        for (int k = 0; k < 64; k++) a += f1[tid * 64 + k] * mx[k];
        sg1[tid] = (a >= 0.f) ? a : 0.1f * a;
    }
    __syncthreads();
    if (tid < 32) {
        float a = 0.f;
        #pragma unroll
        for (int i = 0; i < 8; i++) a += f2[tid * 8 + i] * sg1[i];
        g_gate[t * 32 + tid] = 1.0f / (1.0f + expf(-a));
    }
}

// ---------------- K8: gated mix (tiled transpose) ----------------
__global__ void k_final(float* __restrict__ out) {
    int tc = blockIdx.x;  // 6272 = 196*32
    int t = tc >> 5, c = tc & 31;
    int b = t / 49; int uv = t - b * 49; int u = uv / 7; int v = uv - u * 7;
    __shared__ float sm[32][33];
    int tid = threadIdx.x;
    int lane = tid & 31, row = tid >> 5;
    float g = g_gate[t * 32 + c];
    #pragma unroll
    for (int p = 0; p < 4; p++) {
        int w = row + p * 8;   // o1 contiguous in h(lane): sm[w][h] = o1(h,w)
        sm[w][lane] = g_Xh[((b * NN + v * 32 + w) * CC + c) * LL + u * 32 + lane];
    }
    __syncthreads();
    #pragma unroll
    for (int p = 0; p < 4; p++) {
        int h = row + p * 8;   // o2 contiguous in w(lane)
        float o2 = g_Xv[((b * NN + u * 32 + h) * CC + c) * LL + v * 32 + lane];
        out[((t * CC + c) * 32 + h) * 32 + lane] = sm[lane][h] * g + o2 * (1.0f - g);
    }
}

// ---------------- launch ----------------
extern "C" void kernel_launch(void* const* d_in, const int* in_sizes, int n_in,
                              void* d_out, int out_size) {
    (void)in_sizes; (void)n_in; (void)out_size;
    const float* xlf = (const float*)d_in[0];
    const float* f1  = (const float*)d_in[27];
    const float* f2  = (const float*)d_in[28];
    for (int br = 0; br < 2; br++) {
        int o = 1 + br * 13;
        const float* lin_w  = (const float*)d_in[o + 0];
        const float* temp   = (const float*)d_in[o + 1];
        const float* ln1_g  = (const float*)d_in[o + 2];
        const float* ln1_b  = (const float*)d_in[o + 3];
        const float* qkv_w  = (const float*)d_in[o + 4];
        const float* qkvdw  = (const float*)d_in[o + 5];
        const float* proj_w = (const float*)d_in[o + 6];
        const float* attca  = (const float*)d_in[o + 7];
        const float* lne_g  = (const float*)d_in[o + 8];
        const float* lne_b  = (const float*)d_in[o + 9];
        const float* pin_w  = (const float*)d_in[o + 10];
        const float* dw_w   = (const float*)d_in[o + 11];
        const float* pout_w = (const float*)d_in[o + 12];

        k_pack  <<<6272, 256>>>(xlf, br);
        k_lin   <<<dim3(2, 14, KSPLIT), 256>>>(lin_w);
        k_ln_qkv<<<896, 128>>>(ln1_g, ln1_b, qkv_w);
        k_dw3   <<<(BBATCH * 384 * LL) / 256, 256>>>(qkvdw);
        k_norm  <<<896, 128>>>();
        k_attn  <<<dim3(56, 4), 256>>>(temp, attca);
        k_proj  <<<dim3(112, 7, 4), 128>>>(proj_w, br);
        k_ffn   <<<896, 224>>>(lne_g, lne_b, pin_w, dw_w, pout_w, br);
    }
    k_gate <<<196, 256>>>(f1, f2);
    k_final<<<OUTELEMS / 1024, 256>>>((float*)d_out);
}

// round 13
// speedup vs baseline: 2.2905x; 1.0817x over previous
#include <cuda_runtime.h>
#include <math.h>

#define ANG 7
#define CC 32
#define EE 128
#define NHEADS 4
#define NN 224
#define LL 224
#define TOKD 7168
#define HID 85
#define HID2 170
#define BBATCH 4
#define SAMP 896
#define KSPLIT 16
#define KCH 448          // TOKD / KSPLIT
#define OUTELEMS 6422528
#define JCH 5            // ffn chunk (85 = 17*5)

// ---------------- scratch (16B-aligned: accessed via float4) ----------------
__device__ __align__(16) float g_At[SAMP * TOKD];              // [m=(b,l)][f=(c,r)]
__device__ __align__(16) float g_R[SAMP * CC * LL];            // residual, X layout [s][c][l]
__device__ __align__(16) float g_xpart[KSPLIT * SAMP * EE];    // lin partials [kb][m][e]
__device__ __align__(16) float g_qkvpre[BBATCH * 3 * EE * LL];
__device__ __align__(16) float g_qkv[BBATCH * 3 * EE * LL];
__device__ __align__(16) float g_qn[BBATCH * NHEADS * LL * 32];
__device__ __align__(16) float g_kn[BBATCH * NHEADS * LL * 32];
__device__ __align__(16) float g_vv[BBATCH * NHEADS * LL * 32];
__device__ __align__(16) float g_ao[BBATCH * EE * LL];         // [b][e][l]
__device__ __align__(16) float g_Xh[SAMP * CC * LL];
__device__ __align__(16) float g_Xv[SAMP * CC * LL];
__device__ __align__(16) float g_gate[196 * CC];

__device__ __forceinline__ float gelu_f(float x) {
    return 0.5f * x * (1.0f + erff(x * 0.70710678118654752440f));
}

// ---- packed f32x2 helpers (FFMA2: 2 fp32 FMAs per instruction, rn rounding) ----
__device__ __forceinline__ void ffma2(unsigned long long& d, unsigned long long a, unsigned long long b) {
    asm("fma.rn.f32x2 %0, %1, %2, %0;" : "+l"(d) : "l"(a), "l"(b));
}
__device__ __forceinline__ unsigned long long pack2(float lo, float hi) {
    unsigned long long r;
    asm("mov.b64 %0, {%1, %2};" : "=l"(r) : "r"(__float_as_uint(lo)), "r"(__float_as_uint(hi)));
    return r;
}
__device__ __forceinline__ float2 unpack2(unsigned long long v) {
    unsigned int a, b;
    asm("mov.b64 {%0, %1}, %2;" : "=r"(a), "=r"(b) : "l"(v));
    return make_float2(__uint_as_float(a), __uint_as_float(b));
}

// ---------------- K0: pack (tile transpose) -> g_At and g_R ----------------
__global__ void k_pack(const float* __restrict__ xlf, int br) {
    int bid = blockIdx.x;
    int c = bid & 31; int t = bid >> 5;
    int b = t / 49; int uv = t - b * 49; int u = uv / 7; int v = uv - u * 7;
    __shared__ float sm[32][33];
    int tid = threadIdx.x;
    int lane = tid & 31, row = tid >> 5;
    const float* src = xlf + ((size_t)t * 32 + c) * 1024;
    #pragma unroll
    for (int p = 0; p < 4; p++) {
        int h = row + p * 8;
        sm[h][lane] = src[h * 32 + lane];
    }
    __syncthreads();
    if (br == 0) {
        #pragma unroll
        for (int p = 0; p < 4; p++) {
            int h = row + p * 8;
            g_At[(b * 224 + u * 32 + h) * TOKD + c * 224 + v * 32 + lane] = sm[h][lane];
            int w = row + p * 8;
            g_R[((b * NN + v * 32 + w) * CC + c) * LL + u * 32 + lane] = sm[lane][w];
        }
    } else {
        #pragma unroll
        for (int p = 0; p < 4; p++) {
            int w = row + p * 8;
            g_At[(b * 224 + v * 32 + w) * TOKD + c * 224 + u * 32 + lane] = sm[lane][w];
            int h = row + p * 8;
            g_R[((b * NN + u * 32 + h) * CC + c) * LL + v * 32 + lane] = sm[h][lane];
        }
    }
}

// ---------------- K1: lin GEMM, split-K, 64x64 tiles, FFMA2 micro-tile ----------------
__global__ void k_lin(const float* __restrict__ lin_w) {
    __shared__ __align__(16) float As[16 * 68];  // [k][m]
    __shared__ __align__(16) float Bs[16 * 68];  // [k][e]
    int tid = threadIdx.x;
    int tx = tid & 15, ty = tid >> 4;
    int e0 = blockIdx.x * 64, m0 = blockIdx.y * 64, kb = blockIdx.z;
    int kbase = kb * KCH;
    unsigned long long accp[4][2];
    #pragma unroll
    for (int i = 0; i < 4; i++) { accp[i][0] = 0ull; accp[i][1] = 0ull; }
    int r = tid >> 2, q = tid & 3;
    for (int ks = 0; ks < KCH; ks += 16) {
        float4 av = *(const float4*)&g_At[(m0 + r) * TOKD + kbase + ks + q * 4];
        float4 bv = *(const float4*)&lin_w[(e0 + r) * TOKD + kbase + ks + q * 4];
        As[(q * 4 + 0) * 68 + r] = av.x; As[(q * 4 + 1) * 68 + r] = av.y;
        As[(q * 4 + 2) * 68 + r] = av.z; As[(q * 4 + 3) * 68 + r] = av.w;
        Bs[(q * 4 + 0) * 68 + r] = bv.x; Bs[(q * 4 + 1) * 68 + r] = bv.y;
        Bs[(q * 4 + 2) * 68 + r] = bv.z; Bs[(q * 4 + 3) * 68 + r] = bv.w;
        __syncthreads();
        #pragma unroll
        for (int kk = 0; kk < 16; kk++) {
            float4 a = *(const float4*)&As[kk * 68 + ty * 4];
            ulonglong2 bp = *(const ulonglong2*)&Bs[kk * 68 + tx * 4];
            unsigned long long a0 = pack2(a.x, a.x), a1 = pack2(a.y, a.y);
            unsigned long long a2 = pack2(a.z, a.z), a3 = pack2(a.w, a.w);
            ffma2(accp[0][0], a0, bp.x); ffma2(accp[0][1], a0, bp.y);
            ffma2(accp[1][0], a1, bp.x); ffma2(accp[1][1], a1, bp.y);
            ffma2(accp[2][0], a2, bp.x); ffma2(accp[2][1], a2, bp.y);
            ffma2(accp[3][0], a3, bp.x); ffma2(accp[3][1], a3, bp.y);
        }
        __syncthreads();
    }
    #pragma unroll
    for (int i = 0; i < 4; i++) {
        int m = m0 + ty * 4 + i;
        float2 p0 = unpack2(accp[i][0]), p1 = unpack2(accp[i][1]);
        float4 st4 = make_float4(p0.x, p0.y, p1.x, p1.y);
        *(float4*)&g_xpart[(kb * SAMP + m) * EE + e0 + tx * 4] = st4;
    }
}

// ---------------- K2: reduce partials + LN(E) + qkv 1x1 ----------------
__global__ void k_ln_qkv(const float* __restrict__ gw, const float* __restrict__ bw,
                         const float* __restrict__ qkv_w) {
    int p = blockIdx.x; int b = p / LL, l = p - b * LL;
    int tid = threadIdx.x;  // 128
    __shared__ __align__(16) float s1[128];
    __shared__ __align__(16) float nv[128];
    float v = 0.f;
    #pragma unroll
    for (int kb = 0; kb < KSPLIT; kb++) v += g_xpart[(kb * SAMP + p) * EE + tid];
    s1[tid] = v; __syncthreads();
    for (int s = 64; s > 0; s >>= 1) { if (tid < s) s1[tid] += s1[tid + s]; __syncthreads(); }
    float mean = s1[0] * (1.0f / 128.0f);
    __syncthreads();
    float d = v - mean; s1[tid] = d * d; __syncthreads();
    for (int s = 64; s > 0; s >>= 1) { if (tid < s) s1[tid] += s1[tid + s]; __syncthreads(); }
    float var = s1[0] * (1.0f / 128.0f);
    nv[tid] = d * rsqrtf(var + 1e-6f) * gw[tid] + bw[tid];
    __syncthreads();
    for (int j = tid; j < 384; j += 128) {
        const float4* wr = reinterpret_cast<const float4*>(qkv_w + j * EE);
        float a = 0.f;
        #pragma unroll
        for (int c4 = 0; c4 < 32; c4++) {
            float4 wv = wr[c4];
            a += wv.x * nv[c4 * 4] + wv.y * nv[c4 * 4 + 1] + wv.z * nv[c4 * 4 + 2] + wv.w * nv[c4 * 4 + 3];
        }
        g_qkvpre[(b * 384 + j) * LL + l] = a;
    }
}

// ---------------- K3: depthwise 3x3 ----------------
__global__ void k_dw3(const float* __restrict__ w) {
    int i = blockIdx.x * blockDim.x + threadIdx.x;
    int l = i % LL; int ch = (i / LL) % 384; int b = i / (LL * 384);
    int y = l >> 5, x = l & 31;
    const float* src = g_qkvpre + (b * 384 + ch) * LL;
    float acc = 0.f;
    #pragma unroll
    for (int dy = 0; dy < 3; dy++) {
        int yy = y + dy - 1; if (yy < 0 || yy >= 7) continue;
        #pragma unroll
        for (int dx = 0; dx < 3; dx++) {
            int xx = x + dx - 1; if (xx < 0 || xx >= 32) continue;
            acc += src[yy * 32 + xx] * w[ch * 9 + dy * 3 + dx];
        }
    }
    g_qkv[i] = acc;
}

// ---------------- K4a: l2-normalize q,k ----------------
__global__ void k_norm() {
    int row = blockIdx.x * 4 + (threadIdx.x >> 5);
    int dd = threadIdx.x & 31;
    int l = row % LL; int bh = row / LL; int h = bh & 3; int b = bh >> 2;
    int base = (b * 384 + h * 32 + dd) * LL + l;
    float qv = g_qkv[base];
    float kv = g_qkv[base + 128 * LL];
    float vv = g_qkv[base + 256 * LL];
    float sq = qv * qv, sk = kv * kv;
    #pragma unroll
    for (int o = 16; o > 0; o >>= 1) {
        sq += __shfl_xor_sync(0xffffffffu, sq, o);
        sk += __shfl_xor_sync(0xffffffffu, sk, o);
    }
    float dq = fmaxf(sqrtf(sq), 1e-12f), dk = fmaxf(sqrtf(sk), 1e-12f);
    g_qn[row * 32 + dd] = qv / dq;
    g_kn[row * 32 + dd] = kv / dk;
    g_vv[row * 32 + dd] = vv;
}

// ---------------- K4b: attention, 4 tokens per block ----------------
__global__ void k_attn(const float* __restrict__ temp, const float* __restrict__ attca) {
    int tg0 = blockIdx.x * 4;
    int b = blockIdx.y;
    int tid = threadIdx.x;  // 256
    __shared__ __align__(16) float sq[4 * 128];
    __shared__ __align__(16) float sat[16 * 224];
    __shared__ __align__(16) float outp[256 * 4];
    __shared__ float wred[8 * 16];
    __shared__ float gred[16];
    __shared__ float sca[32];
    if (tid < 32) sca[tid] = attca[tid];
    for (int i = tid; i < 512; i += 256) {
        int t = i >> 7, hd = i & 127;
        sq[i] = g_qn[((b * 4 + (hd >> 5)) * LL + tg0 + t) * 32 + (hd & 31)];
    }
    __syncthreads();

    int m = tid; bool act = (m < LL);
    float lg[16];
    if (act) {
        #pragma unroll
        for (int h = 0; h < 4; h++) {
            const float4* kr = (const float4*)&g_kn[((b * 4 + h) * LL + m) * 32];
            float s[4] = {0.f, 0.f, 0.f, 0.f};
            #pragma unroll
            for (int q = 0; q < 8; q++) {
                float4 kv = kr[q];
                #pragma unroll
                for (int t = 0; t < 4; t++) {
                    float4 qv = *(const float4*)&sq[t * 128 + h * 32 + q * 4];
                    s[t] += kv.x * qv.x + kv.y * qv.y + kv.z * qv.z + kv.w * qv.w;
                }
            }
            float tp = temp[h];
            #pragma unroll
            for (int t = 0; t < 4; t++) lg[h * 4 + t] = s[t] * tp;
        }
    } else {
        #pragma unroll
        for (int i = 0; i < 16; i++) lg[i] = -1e30f;
    }
    int wid = tid >> 5, lane = tid & 31;
    // max reduce
    float red[16];
    #pragma unroll
    for (int i = 0; i < 16; i++) red[i] = lg[i];
    #pragma unroll
    for (int o = 16; o > 0; o >>= 1) {
        #pragma unroll
        for (int i = 0; i < 16; i++) red[i] = fmaxf(red[i], __shfl_xor_sync(0xffffffffu, red[i], o));
    }
    if (lane == 0) {
        #pragma unroll
        for (int i = 0; i < 16; i++) wred[wid * 16 + i] = red[i];
    }
    __syncthreads();
    if (tid < 16) {
        float vmx = wred[tid];
        #pragma unroll
        for (int w = 1; w < 8; w++) vmx = fmaxf(vmx, wred[w * 16 + tid]);
        gred[tid] = vmx;
    }
    __syncthreads();
    float e[16];
    #pragma unroll
    for (int i = 0; i < 16; i++) e[i] = act ? expf(lg[i] - gred[i]) : 0.f;
    __syncthreads();
    // sum reduce
    #pragma unroll
    for (int i = 0; i < 16; i++) red[i] = e[i];
    #pragma unroll
    for (int o = 16; o > 0; o >>= 1) {
        #pragma unroll
        for (int i = 0; i < 16; i++) red[i] += __shfl_xor_sync(0xffffffffu, red[i], o);
    }
    if (lane == 0) {
        #pragma unroll
        for (int i = 0; i < 16; i++) wred[wid * 16 + i] = red[i];
    }
    __syncthreads();
    if (tid < 16) {
        float vs = wred[tid];
        #pragma unroll
        for (int w = 1; w < 8; w++) vs += wred[w * 16 + tid];
        gred[tid] = vs;
    }
    __syncthreads();
    if (act) {
        float ag[16];
        #pragma unroll
        for (int i = 0; i < 16; i++) { float a = fmaxf(lg[i], 0.f); a *= a; ag[i] = gelu_f(a) * a; }
        #pragma unroll
        for (int t = 0; t < 4; t++) {
            #pragma unroll
            for (int h = 0; h < 4; h++) {
                float sc = sca[h * 4 + 0] * ag[0 * 4 + t] + sca[h * 4 + 1] * ag[1 * 4 + t] +
                           sca[h * 4 + 2] * ag[2 * 4 + t] + sca[h * 4 + 3] * ag[3 * 4 + t];
                float sh = sca[(4 + h) * 4 + 0] * ag[0 * 4 + t] + sca[(4 + h) * 4 + 1] * ag[1 * 4 + t] +
                           sca[(4 + h) * 4 + 2] * ag[2 * 4 + t] + sca[(4 + h) * 4 + 3] * ag[3 * 4 + t];
                float p = e[h * 4 + t] / gred[h * 4 + t];
                sat[(t * 4 + h) * 224 + m] = p * (1.0f + sc) + sh;
            }
        }
    }
    __syncthreads();
    // AV: all 256 threads; two mm-halves
    {
        int half = tid >> 7, hd = tid & 127, h = hd >> 5, dd = hd & 31;
        float o[4] = {0.f, 0.f, 0.f, 0.f};
        const float* vb = &g_vv[((b * 4 + h) * LL) * 32 + dd];
        int mmend = half * 112 + 112;
        for (int mm = half * 112; mm < mmend; mm++) {
            float v = vb[mm * 32];
            #pragma unroll
            for (int t = 0; t < 4; t++) o[t] += sat[(t * 4 + h) * 224 + mm] * v;
        }
        #pragma unroll
        for (int t = 0; t < 4; t++) outp[tid * 4 + t] = o[t];
    }
    __syncthreads();
    if (tid < 128) {
        float4 r4;
        r4.x = outp[tid * 4 + 0] + outp[(tid + 128) * 4 + 0];
        r4.y = outp[tid * 4 + 1] + outp[(tid + 128) * 4 + 1];
        r4.z = outp[tid * 4 + 2] + outp[(tid + 128) * 4 + 2];
        r4.w = outp[tid * 4 + 3] + outp[(tid + 128) * 4 + 3];
        *(float4*)&g_ao[(b * EE + tid) * LL + tg0] = r4;
    }
}

// ---------------- K5: proj GEMM + residual (FFMA2 micro-tile) ----------------
__global__ void k_proj(const float* __restrict__ proj_w, int br) {
    __shared__ __align__(16) float As[16 * 68];  // [k][t]
    __shared__ __align__(16) float Bs[16 * 36];  // [k][l]
    int tid = threadIdx.x;
    int tx = tid & 7, ty = tid >> 3;
    int t0 = blockIdx.x * 64, l0 = blockIdx.y * 32, b = blockIdx.z;
    unsigned long long accp[4][2];
    #pragma unroll
    for (int i = 0; i < 4; i++) { accp[i][0] = 0ull; accp[i][1] = 0ull; }
    for (int ks = 0; ks < EE; ks += 16) {
        #pragma unroll
        for (int ii = 0; ii < 2; ii++) {
            int idx = tid * 2 + ii;
            int r = idx >> 2, q = idx & 3;
            float4 a4 = *(const float4*)&proj_w[(t0 + r) * EE + ks + q * 4];
            As[(q * 4 + 0) * 68 + r] = a4.x; As[(q * 4 + 1) * 68 + r] = a4.y;
            As[(q * 4 + 2) * 68 + r] = a4.z; As[(q * 4 + 3) * 68 + r] = a4.w;
        }
        {
            int r = tid >> 3, q = tid & 7;
            float4 b4 = *(const float4*)&g_ao[(b * EE + ks + r) * LL + l0 + q * 4];
            *(float4*)&Bs[r * 36 + q * 4] = b4;
        }
        __syncthreads();
        #pragma unroll
        for (int kk = 0; kk < 16; kk++) {
            float4 a = *(const float4*)&As[kk * 68 + ty * 4];
            ulonglong2 bp = *(const ulonglong2*)&Bs[kk * 36 + tx * 4];
            unsigned long long a0 = pack2(a.x, a.x), a1 = pack2(a.y, a.y);
            unsigned long long a2 = pack2(a.z, a.z), a3 = pack2(a.w, a.w);
            ffma2(accp[0][0], a0, bp.x); ffma2(accp[0][1], a0, bp.y);
            ffma2(accp[1][0], a1, bp.x); ffma2(accp[1][1], a1, bp.y);
            ffma2(accp[2][0], a2, bp.x); ffma2(accp[2][1], a2, bp.y);
            ffma2(accp[3][0], a3, bp.x); ffma2(accp[3][1], a3, bp.y);
        }
        __syncthreads();
    }
    float* X = br ? g_Xv : g_Xh;
    #pragma unroll
    for (int i = 0; i < 4; i++) {
        int t = t0 + ty * 4 + i;
        int c = t / NN, r = t - c * NN;
        int base = ((b * NN + r) * CC + c) * LL + l0 + tx * 4;
        float4 res = *(const float4*)&g_R[base];
        float2 p0 = unpack2(accp[i][0]), p1 = unpack2(accp[i][1]);
        float4 o;
        o.x = p0.x + res.x; o.y = p0.y + res.y;
        o.z = p1.x + res.z; o.w = p1.y + res.w;
        *(float4*)&X[base] = o;
    }
}

// ---------------- K6: fused FFN (chunked barriers + FFMA2) ----------------
__global__ void k_ffn(const float* __restrict__ lg_, const float* __restrict__ lb_,
                      const float* __restrict__ pin_w, const float* __restrict__ dw_w,
                      const float* __restrict__ pout_w, int br) {
    int s = blockIdx.x;
    int l = threadIdx.x;  // 224
    __shared__ __align__(16) float spin[HID2 * 32];
    __shared__ __align__(16) float spoT[HID * 32];
    __shared__ __align__(16) float stA[JCH * LL];
    __shared__ __align__(16) float stG[JCH * LL];
    __shared__ float sdw[HID2 * 9];     // scalar-only access; declared last
    for (int i = l; i < HID2 * 32; i += 224) spin[i] = pin_w[i];
    for (int i = l; i < HID2 * 9; i += 224) sdw[i] = dw_w[i];
    for (int i = l; i < HID * 32; i += 224) {
        int c = i & 31, j = i >> 5;
        spoT[i] = pout_w[c * HID + j];
    }
    float* X = (br ? g_Xv : g_Xh) + s * CC * LL + l;
    float xv[32];
    float mean = 0.f;
    #pragma unroll
    for (int c = 0; c < 32; c++) { xv[c] = X[c * LL]; mean += xv[c]; }
    mean *= (1.0f / 32.0f);
    float var = 0.f;
    #pragma unroll
    for (int c = 0; c < 32; c++) { float d = xv[c] - mean; xv[c] = d; var += d * d; }
    var *= (1.0f / 32.0f);
    float rs = rsqrtf(var + 1e-6f);
    #pragma unroll
    for (int c = 0; c < 32; c++) xv[c] = xv[c] * rs * lg_[c] + lb_[c];
    // pack LN'd activations into f32x2 pairs
    unsigned long long xp[16];
    #pragma unroll
    for (int q = 0; q < 16; q++) xp[q] = pack2(xv[2 * q], xv[2 * q + 1]);
    __syncthreads();
    unsigned long long accp[16];
    #pragma unroll
    for (int q = 0; q < 16; q++) accp[q] = 0ull;
    int y = l >> 5, x = l & 31;
    for (int jc = 0; jc < HID / JCH; jc++) {
        #pragma unroll
        for (int jj = 0; jj < JCH; jj++) {
            int j = jc * JCH + jj;
            const unsigned long long* w1 = (const unsigned long long*)&spin[j * 32];
            const unsigned long long* w2 = (const unsigned long long*)&spin[(HID + j) * 32];
            unsigned long long aP = 0ull, gP = 0ull;
            #pragma unroll
            for (int q = 0; q < 16; q++) {
                ffma2(aP, w1[q], xp[q]);
                ffma2(gP, w2[q], xp[q]);
            }
            float2 af = unpack2(aP), gf = unpack2(gP);
            stA[jj * LL + l] = af.x + af.y;
            stG[jj * LL + l] = gf.x + gf.y;
        }
        __syncthreads();
        #pragma unroll
        for (int jj = 0; jj < JCH; jj++) {
            int j = jc * JCH + jj;
            float ca = 0.f, cg = 0.f;
            #pragma unroll
            for (int dy = 0; dy < 3; dy++) {
                int yy = y + dy - 1; if (yy < 0 || yy >= 7) continue;
                #pragma unroll
                for (int dx = 0; dx < 3; dx++) {
                    int xx = x + dx - 1; if (xx < 0 || xx >= 32) continue;
                    int li = jj * LL + yy * 32 + xx;
                    ca += stA[li] * sdw[j * 9 + dy * 3 + dx];
                    cg += stG[li] * sdw[(HID + j) * 9 + dy * 3 + dx];
                }
            }
            float gj = gelu_f(ca) * cg;
            unsigned long long gp = pack2(gj, gj);
            const unsigned long long* p4 = (const unsigned long long*)&spoT[j * 32];
            #pragma unroll
            for (int q = 0; q < 16; q++) ffma2(accp[q], gp, p4[q]);
        }
        __syncthreads();
    }
    #pragma unroll
    for (int q = 0; q < 16; q++) {
        float2 p = unpack2(accp[q]);
        X[(2 * q) * LL]     += p.x;
        X[(2 * q + 1) * LL] += p.y;
    }
}

// ---------------- K7: gate (coalesced max pool + MLP) ----------------
__global__ void k_gate(const float* __restrict__ f1, const float* __restrict__ f2) {
    int t = blockIdx.x;
    int b = t / 49; int uv = t - b * 49; int u = uv / 7; int v = uv - u * 7;
    int tid = threadIdx.x;  // 256
    int wid = tid >> 5, lane = tid & 31;
    __shared__ float mx[64], sg1[8];
    #pragma unroll
    for (int k = 0; k < 8; k++) {
        int combo = wid * 8 + k;
        int c = combo & 31; bool is2 = combo >= 32;
        float m = -1e30f;
        if (!is2) {
            for (int w = 0; w < 32; w++)
                m = fmaxf(m, g_Xh[((b * NN + v * 32 + w) * CC + c) * LL + u * 32 + lane]);
        } else {
            for (int h = 0; h < 32; h++)
                m = fmaxf(m, g_Xv[((b * NN + u * 32 + h) * CC + c) * LL + v * 32 + lane]);
        }
        #pragma unroll
        for (int o = 16; o > 0; o >>= 1) m = fmaxf(m, __shfl_xor_sync(0xffffffffu, m, o));
        if (lane == 0) mx[combo] = m;
    }
    __syncthreads();
    if (tid < 8) {
        float a = 0.f;
        for (int k = 0; k < 64; k++) a += f1[tid * 64 + k] * mx[k];
        sg1[tid] = (a >= 0.f) ? a : 0.1f * a;
    }
    __syncthreads();
    if (tid < 32) {
        float a = 0.f;
        #pragma unroll
        for (int i = 0; i < 8; i++) a += f2[tid * 8 + i] * sg1[i];
        g_gate[t * 32 + tid] = 1.0f / (1.0f + expf(-a));
    }
}

// ---------------- K8: gated mix (tiled transpose) ----------------
__global__ void k_final(float* __restrict__ out) {
    int tc = blockIdx.x;  // 6272 = 196*32
    int t = tc >> 5, c = tc & 31;
    int b = t / 49; int uv = t - b * 49; int u = uv / 7; int v = uv - u * 7;
    __shared__ float sm[32][33];
    int tid = threadIdx.x;
    int lane = tid & 31, row = tid >> 5;
    float g = g_gate[t * 32 + c];
    #pragma unroll
    for (int p = 0; p < 4; p++) {
        int w = row + p * 8;
        sm[w][lane] = g_Xh[((b * NN + v * 32 + w) * CC + c) * LL + u * 32 + lane];
    }
    __syncthreads();
    #pragma unroll
    for (int p = 0; p < 4; p++) {
        int h = row + p * 8;
        float o2 = g_Xv[((b * NN + u * 32 + h) * CC + c) * LL + v * 32 + lane];
        out[((t * CC + c) * 32 + h) * 32 + lane] = sm[lane][h] * g + o2 * (1.0f - g);
    }
}

// ---------------- launch ----------------
extern "C" void kernel_launch(void* const* d_in, const int* in_sizes, int n_in,
                              void* d_out, int out_size) {
    (void)in_sizes; (void)n_in; (void)out_size;
    const float* xlf = (const float*)d_in[0];
    const float* f1  = (const float*)d_in[27];
    const float* f2  = (const float*)d_in[28];
    for (int br = 0; br < 2; br++) {
        int o = 1 + br * 13;
        const float* lin_w  = (const float*)d_in[o + 0];
        const float* temp   = (const float*)d_in[o + 1];
        const float* ln1_g  = (const float*)d_in[o + 2];
        const float* ln1_b  = (const float*)d_in[o + 3];
        const float* qkv_w  = (const float*)d_in[o + 4];
        const float* qkvdw  = (const float*)d_in[o + 5];
        const float* proj_w = (const float*)d_in[o + 6];
        const float* attca  = (const float*)d_in[o + 7];
        const float* lne_g  = (const float*)d_in[o + 8];
        const float* lne_b  = (const float*)d_in[o + 9];
        const float* pin_w  = (const float*)d_in[o + 10];
        const float* dw_w   = (const float*)d_in[o + 11];
        const float* pout_w = (const float*)d_in[o + 12];

        k_pack  <<<6272, 256>>>(xlf, br);
        k_lin   <<<dim3(2, 14, KSPLIT), 256>>>(lin_w);
        k_ln_qkv<<<896, 128>>>(ln1_g, ln1_b, qkv_w);
        k_dw3   <<<(BBATCH * 384 * LL) / 256, 256>>>(qkvdw);
        k_norm  <<<896, 128>>>();
        k_attn  <<<dim3(56, 4), 256>>>(temp, attca);
        k_proj  <<<dim3(112, 7, 4), 128>>>(proj_w, br);
        k_ffn   <<<896, 224>>>(lne_g, lne_b, pin_w, dw_w, pout_w, br);
    }
    k_gate <<<196, 256>>>(f1, f2);
    k_final<<<OUTELEMS / 1024, 256>>>((float*)d_out);
}

// round 15
// speedup vs baseline: 2.4251x; 1.0588x over previous
#include <cuda_runtime.h>
#include <math.h>

#define ANG 7
#define CC 32
#define EE 128
#define NHEADS 4
#define NN 224
#define LL 224
#define TOKD 7168
#define HID 85
#define HID2 170
#define BBATCH 4
#define SAMP 896
#define KSPLIT 16
#define KCH 448          // TOKD / KSPLIT
#define OUTELEMS 6422528
#define JCH 5            // ffn chunk (85 = 17*5)

// per-branch sizes
#define AT_SZ (SAMP * TOKD)
#define R_SZ  (SAMP * CC * LL)
#define XP_SZ (KSPLIT * SAMP * EE)
#define QP_SZ (BBATCH * 3 * EE * LL)
#define QN_SZ (BBATCH * NHEADS * LL * 32)
#define AO_SZ (BBATCH * EE * LL)

// ---------------- scratch (16B-aligned; [branch] major) ----------------
__device__ __align__(16) float g_At[2 * AT_SZ];
__device__ __align__(16) float g_R[2 * R_SZ];
__device__ __align__(16) float g_xpart[2 * XP_SZ];
__device__ __align__(16) float g_qkvpre[2 * QP_SZ];
__device__ __align__(16) float g_qkv[2 * QP_SZ];
__device__ __align__(16) float g_qn[2 * QN_SZ];
__device__ __align__(16) float g_kn[2 * QN_SZ];
__device__ __align__(16) float g_vv[2 * QN_SZ];
__device__ __align__(16) float g_ao[2 * AO_SZ];
__device__ __align__(16) float g_Xh[R_SZ];
__device__ __align__(16) float g_Xv[R_SZ];
__device__ __align__(16) float g_gate[196 * CC];

__device__ __forceinline__ float gelu_f(float x) {
    return 0.5f * x * (1.0f + erff(x * 0.70710678118654752440f));
}

// ---- packed f32x2 helpers ----
__device__ __forceinline__ void ffma2(unsigned long long& d, unsigned long long a, unsigned long long b) {
    asm("fma.rn.f32x2 %0, %1, %2, %0;" : "+l"(d) : "l"(a), "l"(b));
}
__device__ __forceinline__ unsigned long long pack2(float lo, float hi) {
    unsigned long long r;
    asm("mov.b64 %0, {%1, %2};" : "=l"(r) : "r"(__float_as_uint(lo)), "r"(__float_as_uint(hi)));
    return r;
}
__device__ __forceinline__ float2 unpack2(unsigned long long v) {
    unsigned int a, b;
    asm("mov.b64 {%0, %1}, %2;" : "=r"(a), "=r"(b) : "l"(v));
    return make_float2(__uint_as_float(a), __uint_as_float(b));
}

// ---------------- K0: merged pack (one read, 4 writes) ----------------
__global__ void k_pack(const float* __restrict__ xlf) {
    int bid = blockIdx.x;
    int c = bid & 31; int t = bid >> 5;
    int b = t / 49; int uv = t - b * 49; int u = uv / 7; int v = uv - u * 7;
    __shared__ float sm[32][33];
    int tid = threadIdx.x;
    int lane = tid & 31, row = tid >> 5;
    const float* src = xlf + ((size_t)t * 32 + c) * 1024;
    #pragma unroll
    for (int p = 0; p < 4; p++) {
        int h = row + p * 8;
        sm[h][lane] = src[h * 32 + lane];
    }
    __syncthreads();
    #pragma unroll
    for (int p = 0; p < 4; p++) {
        int h = row + p * 8;   // doubles as w for transposed writes
        // br0 At direct: l=u*32+h, r=v*32+lane, value x(h, lane)
        g_At[(b * 224 + u * 32 + h) * TOKD + c * 224 + v * 32 + lane] = sm[h][lane];
        // br0 R transposed: n=v*32+h(w), l=u*32+lane, value x(lane, h)
        g_R[((b * NN + v * 32 + h) * CC + c) * LL + u * 32 + lane] = sm[lane][h];
        // br1 At transposed: l=v*32+h(w), r=u*32+lane, value x(lane, h)
        g_At[AT_SZ + (b * 224 + v * 32 + h) * TOKD + c * 224 + u * 32 + lane] = sm[lane][h];
        // br1 R direct: n=u*32+h, l=v*32+lane, value x(h, lane)
        g_R[R_SZ + ((b * NN + u * 32 + h) * CC + c) * LL + v * 32 + lane] = sm[h][lane];
    }
}

// ---------------- K1: lin GEMM, split-K, ping-pong double-buffer ----------------
__global__ void k_lin(const float* __restrict__ lin_w0, const float* __restrict__ lin_w1) {
    __shared__ __align__(16) float As[2][16 * 68];  // [buf][k][m]
    __shared__ __align__(16) float Bs[2][16 * 68];  // [buf][k][e]
    int tid = threadIdx.x;
    int tx = tid & 15, ty = tid >> 4;
    int e0 = blockIdx.x * 64, m0 = blockIdx.y * 64;
    int kb = blockIdx.z & 15, br = blockIdx.z >> 4;
    const float* lw = br ? lin_w1 : lin_w0;
    const float* At = g_At + (size_t)br * AT_SZ;
    int kbase = kb * KCH;
    unsigned long long accp[4][2];
    #pragma unroll
    for (int i = 0; i < 4; i++) { accp[i][0] = 0ull; accp[i][1] = 0ull; }
    int r = tid >> 2, q = tid & 3;
    const float* aptr = &At[(m0 + r) * TOKD + kbase + q * 4];
    const float* bptr = &lw[(e0 + r) * TOKD + kbase + q * 4];
    {
        float4 av = *(const float4*)aptr;
        float4 bv = *(const float4*)bptr;
        As[0][(q * 4 + 0) * 68 + r] = av.x; As[0][(q * 4 + 1) * 68 + r] = av.y;
        As[0][(q * 4 + 2) * 68 + r] = av.z; As[0][(q * 4 + 3) * 68 + r] = av.w;
        Bs[0][(q * 4 + 0) * 68 + r] = bv.x; Bs[0][(q * 4 + 1) * 68 + r] = bv.y;
        Bs[0][(q * 4 + 2) * 68 + r] = bv.z; Bs[0][(q * 4 + 3) * 68 + r] = bv.w;
    }
    __syncthreads();
    int p = 0;
    for (int ks = 16; ks < KCH; ks += 16) {
        float4 av = *(const float4*)(aptr + ks);
        float4 bv = *(const float4*)(bptr + ks);
        #pragma unroll
        for (int kk = 0; kk < 16; kk++) {
            float4 a = *(const float4*)&As[p][kk * 68 + ty * 4];
            ulonglong2 bp = *(const ulonglong2*)&Bs[p][kk * 68 + tx * 4];
            unsigned long long a0 = pack2(a.x, a.x), a1 = pack2(a.y, a.y);
            unsigned long long a2 = pack2(a.z, a.z), a3 = pack2(a.w, a.w);
            ffma2(accp[0][0], a0, bp.x); ffma2(accp[0][1], a0, bp.y);
            ffma2(accp[1][0], a1, bp.x); ffma2(accp[1][1], a1, bp.y);
            ffma2(accp[2][0], a2, bp.x); ffma2(accp[2][1], a2, bp.y);
            ffma2(accp[3][0], a3, bp.x); ffma2(accp[3][1], a3, bp.y);
        }
        int np = 1 - p;
        As[np][(q * 4 + 0) * 68 + r] = av.x; As[np][(q * 4 + 1) * 68 + r] = av.y;
        As[np][(q * 4 + 2) * 68 + r] = av.z; As[np][(q * 4 + 3) * 68 + r] = av.w;
        Bs[np][(q * 4 + 0) * 68 + r] = bv.x; Bs[np][(q * 4 + 1) * 68 + r] = bv.y;
        Bs[np][(q * 4 + 2) * 68 + r] = bv.z; Bs[np][(q * 4 + 3) * 68 + r] = bv.w;
        __syncthreads();
        p = np;
    }
    #pragma unroll
    for (int kk = 0; kk < 16; kk++) {
        float4 a = *(const float4*)&As[p][kk * 68 + ty * 4];
        ulonglong2 bp = *(const ulonglong2*)&Bs[p][kk * 68 + tx * 4];
        unsigned long long a0 = pack2(a.x, a.x), a1 = pack2(a.y, a.y);
        unsigned long long a2 = pack2(a.z, a.z), a3 = pack2(a.w, a.w);
        ffma2(accp[0][0], a0, bp.x); ffma2(accp[0][1], a0, bp.y);
        ffma2(accp[1][0], a1, bp.x); ffma2(accp[1][1], a1, bp.y);
        ffma2(accp[2][0], a2, bp.x); ffma2(accp[2][1], a2, bp.y);
        ffma2(accp[3][0], a3, bp.x); ffma2(accp[3][1], a3, bp.y);
    }
    float* xp = g_xpart + (size_t)br * XP_SZ;
    #pragma unroll
    for (int i = 0; i < 4; i++) {
        int m = m0 + ty * 4 + i;
        float2 p0 = unpack2(accp[i][0]), p1 = unpack2(accp[i][1]);
        float4 st4 = make_float4(p0.x, p0.y, p1.x, p1.y);
        *(float4*)&xp[(kb * SAMP + m) * EE + e0 + tx * 4] = st4;
    }
}

// ---------------- K2: reduce partials + LN(E) + qkv 1x1 ----------------
__global__ void k_ln_qkv(const float* __restrict__ gw0, const float* __restrict__ bw0,
                         const float* __restrict__ qw0,
                         const float* __restrict__ gw1, const float* __restrict__ bw1,
                         const float* __restrict__ qw1) {
    int p = blockIdx.x; int br = blockIdx.y;
    int b = p / LL, l = p - b * LL;
    const float* gw = br ? gw1 : gw0;
    const float* bw = br ? bw1 : bw0;
    const float* qkv_w = br ? qw1 : qw0;
    const float* xp = g_xpart + (size_t)br * XP_SZ;
    int tid = threadIdx.x;  // 128
    __shared__ __align__(16) float s1[128];
    __shared__ __align__(16) float nv[128];
    float v = 0.f;
    #pragma unroll
    for (int kb = 0; kb < KSPLIT; kb++) v += xp[(kb * SAMP + p) * EE + tid];
    s1[tid] = v; __syncthreads();
    for (int s = 64; s > 0; s >>= 1) { if (tid < s) s1[tid] += s1[tid + s]; __syncthreads(); }
    float mean = s1[0] * (1.0f / 128.0f);
    __syncthreads();
    float d = v - mean; s1[tid] = d * d; __syncthreads();
    for (int s = 64; s > 0; s >>= 1) { if (tid < s) s1[tid] += s1[tid + s]; __syncthreads(); }
    float var = s1[0] * (1.0f / 128.0f);
    nv[tid] = d * rsqrtf(var + 1e-6f) * gw[tid] + bw[tid];
    __syncthreads();
    float* outp = g_qkvpre + (size_t)br * QP_SZ;
    for (int j = tid; j < 384; j += 128) {
        const float4* wr = reinterpret_cast<const float4*>(qkv_w + j * EE);
        float a = 0.f;
        #pragma unroll
        for (int c4 = 0; c4 < 32; c4++) {
            float4 wv = wr[c4];
            a += wv.x * nv[c4 * 4] + wv.y * nv[c4 * 4 + 1] + wv.z * nv[c4 * 4 + 2] + wv.w * nv[c4 * 4 + 3];
        }
        outp[(b * 384 + j) * LL + l] = a;
    }
}

// ---------------- K3: depthwise 3x3 ----------------
__global__ void k_dw3(const float* __restrict__ w0, const float* __restrict__ w1) {
    int i = blockIdx.x * blockDim.x + threadIdx.x;
    int br = blockIdx.y;
    const float* w = br ? w1 : w0;
    int l = i % LL; int ch = (i / LL) % 384; int b = i / (LL * 384);
    int y = l >> 5, x = l & 31;
    const float* src = g_qkvpre + (size_t)br * QP_SZ + (b * 384 + ch) * LL;
    float acc = 0.f;
    #pragma unroll
    for (int dy = 0; dy < 3; dy++) {
        int yy = y + dy - 1; if (yy < 0 || yy >= 7) continue;
        #pragma unroll
        for (int dx = 0; dx < 3; dx++) {
            int xx = x + dx - 1; if (xx < 0 || xx >= 32) continue;
            acc += src[yy * 32 + xx] * w[ch * 9 + dy * 3 + dx];
        }
    }
    g_qkv[(size_t)br * QP_SZ + i] = acc;
}

// ---------------- K4a: l2-normalize q,k ----------------
__global__ void k_norm() {
    int row = blockIdx.x * 4 + (threadIdx.x >> 5);
    int br = blockIdx.y;
    int dd = threadIdx.x & 31;
    int l = row % LL; int bh = row / LL; int h = bh & 3; int b = bh >> 2;
    int base = (b * 384 + h * 32 + dd) * LL + l;
    const float* qk = g_qkv + (size_t)br * QP_SZ;
    float qv = qk[base];
    float kv = qk[base + 128 * LL];
    float vv = qk[base + 256 * LL];
    float sq = qv * qv, sk = kv * kv;
    #pragma unroll
    for (int o = 16; o > 0; o >>= 1) {
        sq += __shfl_xor_sync(0xffffffffu, sq, o);
        sk += __shfl_xor_sync(0xffffffffu, sk, o);
    }
    float dq = fmaxf(sqrtf(sq), 1e-12f), dk = fmaxf(sqrtf(sk), 1e-12f);
    size_t o2 = (size_t)br * QN_SZ;
    g_qn[o2 + row * 32 + dd] = qv / dq;
    g_kn[o2 + row * 32 + dd] = kv / dk;
    g_vv[o2 + row * 32 + dd] = vv;
}

// ---------------- K4b: attention, 4 tokens per block ----------------
__global__ void k_attn(const float* __restrict__ temp0, const float* __restrict__ attca0,
                       const float* __restrict__ temp1, const float* __restrict__ attca1) {
    int tg0 = blockIdx.x * 4;
    int b = blockIdx.y;
    int br = blockIdx.z;
    const float* temp = br ? temp1 : temp0;
    const float* attca = br ? attca1 : attca0;
    const float* qn = g_qn + (size_t)br * QN_SZ;
    const float* kn = g_kn + (size_t)br * QN_SZ;
    const float* vvb = g_vv + (size_t)br * QN_SZ;
    int tid = threadIdx.x;  // 256
    __shared__ __align__(16) float sq[4 * 128];
    __shared__ __align__(16) float sat[16 * 224];
    __shared__ __align__(16) float outp[256 * 4];
    __shared__ float wred[8 * 16];
    __shared__ float gred[16];
    __shared__ float sca[32];
    if (tid < 32) sca[tid] = attca[tid];
    for (int i = tid; i < 512; i += 256) {
        int t = i >> 7, hd = i & 127;
        sq[i] = qn[((b * 4 + (hd >> 5)) * LL + tg0 + t) * 32 + (hd & 31)];
    }
    __syncthreads();

    int m = tid; bool act = (m < LL);
    float lg[16];
    if (act) {
        #pragma unroll
        for (int h = 0; h < 4; h++) {
            const float4* kr = (const float4*)&kn[((b * 4 + h) * LL + m) * 32];
            float s[4] = {0.f, 0.f, 0.f, 0.f};
            #pragma unroll
            for (int q = 0; q < 8; q++) {
                float4 kv = kr[q];
                #pragma unroll
                for (int t = 0; t < 4; t++) {
                    float4 qv = *(const float4*)&sq[t * 128 + h * 32 + q * 4];
                    s[t] += kv.x * qv.x + kv.y * qv.y + kv.z * qv.z + kv.w * qv.w;
                }
            }
            float tp = temp[h];
            #pragma unroll
            for (int t = 0; t < 4; t++) lg[h * 4 + t] = s[t] * tp;
        }
    } else {
        #pragma unroll
        for (int i = 0; i < 16; i++) lg[i] = -1e30f;
    }
    int wid = tid >> 5, lane = tid & 31;
    float red[16];
    #pragma unroll
    for (int i = 0; i < 16; i++) red[i] = lg[i];
    #pragma unroll
    for (int o = 16; o > 0; o >>= 1) {
        #pragma unroll
        for (int i = 0; i < 16; i++) red[i] = fmaxf(red[i], __shfl_xor_sync(0xffffffffu, red[i], o));
    }
    if (lane == 0) {
        #pragma unroll
        for (int i = 0; i < 16; i++) wred[wid * 16 + i] = red[i];
    }
    __syncthreads();
    if (tid < 16) {
        float vmx = wred[tid];
        #pragma unroll
        for (int w = 1; w < 8; w++) vmx = fmaxf(vmx, wred[w * 16 + tid]);
        gred[tid] = vmx;
    }
    __syncthreads();
    float e[16];
    #pragma unroll
    for (int i = 0; i < 16; i++) e[i] = act ? expf(lg[i] - gred[i]) : 0.f;
    __syncthreads();
    #pragma unroll
    for (int i = 0; i < 16; i++) red[i] = e[i];
    #pragma unroll
    for (int o = 16; o > 0; o >>= 1) {
        #pragma unroll
        for (int i = 0; i < 16; i++) red[i] += __shfl_xor_sync(0xffffffffu, red[i], o);
    }
    if (lane == 0) {
        #pragma unroll
        for (int i = 0; i < 16; i++) wred[wid * 16 + i] = red[i];
    }
    __syncthreads();
    if (tid < 16) {
        float vs = wred[tid];
        #pragma unroll
        for (int w = 1; w < 8; w++) vs += wred[w * 16 + tid];
        gred[tid] = vs;
    }
    __syncthreads();
    if (act) {
        float ag[16];
        #pragma unroll
        for (int i = 0; i < 16; i++) { float a = fmaxf(lg[i], 0.f); a *= a; ag[i] = gelu_f(a) * a; }
        #pragma unroll
        for (int t = 0; t < 4; t++) {
            #pragma unroll
            for (int h = 0; h < 4; h++) {
                float sc = sca[h * 4 + 0] * ag[0 * 4 + t] + sca[h * 4 + 1] * ag[1 * 4 + t] +
                           sca[h * 4 + 2] * ag[2 * 4 + t] + sca[h * 4 + 3] * ag[3 * 4 + t];
                float sh = sca[(4 + h) * 4 + 0] * ag[0 * 4 + t] + sca[(4 + h) * 4 + 1] * ag[1 * 4 + t] +
                           sca[(4 + h) * 4 + 2] * ag[2 * 4 + t] + sca[(4 + h) * 4 + 3] * ag[3 * 4 + t];
                float p = e[h * 4 + t] / gred[h * 4 + t];
                sat[(t * 4 + h) * 224 + m] = p * (1.0f + sc) + sh;
            }
        }
    }
    __syncthreads();
    {
        int half = tid >> 7, hd = tid & 127, h = hd >> 5, dd = hd & 31;
        float o[4] = {0.f, 0.f, 0.f, 0.f};
        const float* vb = &vvb[((b * 4 + h) * LL) * 32 + dd];
        int mmend = half * 112 + 112;
        for (int mm = half * 112; mm < mmend; mm++) {
            float v = vb[mm * 32];
            #pragma unroll
            for (int t = 0; t < 4; t++) o[t] += sat[(t * 4 + h) * 224 + mm] * v;
        }
        #pragma unroll
        for (int t = 0; t < 4; t++) outp[tid * 4 + t] = o[t];
    }
    __syncthreads();
    if (tid < 128) {
        float4 r4;
        r4.x = outp[tid * 4 + 0] + outp[(tid + 128) * 4 + 0];
        r4.y = outp[tid * 4 + 1] + outp[(tid + 128) * 4 + 1];
        r4.z = outp[tid * 4 + 2] + outp[(tid + 128) * 4 + 2];
        r4.w = outp[tid * 4 + 3] + outp[(tid + 128) * 4 + 3];
        *(float4*)&g_ao[(size_t)br * AO_SZ + (b * EE + tid) * LL + tg0] = r4;
    }
}

// ---------------- K5: proj GEMM + residual ----------------
__global__ void k_proj(const float* __restrict__ pw0, const float* __restrict__ pw1) {
    __shared__ __align__(16) float As[16 * 68];
    __shared__ __align__(16) float Bs[16 * 36];
    int tid = threadIdx.x;
    int tx = tid & 7, ty = tid >> 3;
    int t0 = blockIdx.x * 64, l0 = blockIdx.y * 32;
    int b = blockIdx.z & 3, br = blockIdx.z >> 2;
    const float* proj_w = br ? pw1 : pw0;
    const float* ao = g_ao + (size_t)br * AO_SZ;
    unsigned long long accp[4][2];
    #pragma unroll
    for (int i = 0; i < 4; i++) { accp[i][0] = 0ull; accp[i][1] = 0ull; }
    for (int ks = 0; ks < EE; ks += 16) {
        #pragma unroll
        for (int ii = 0; ii < 2; ii++) {
            int idx = tid * 2 + ii;
            int r = idx >> 2, q = idx & 3;
            float4 a4 = *(const float4*)&proj_w[(t0 + r) * EE + ks + q * 4];
            As[(q * 4 + 0) * 68 + r] = a4.x; As[(q * 4 + 1) * 68 + r] = a4.y;
            As[(q * 4 + 2) * 68 + r] = a4.z; As[(q * 4 + 3) * 68 + r] = a4.w;
        }
        {
            int r = tid >> 3, q = tid & 7;
            float4 b4 = *(const float4*)&ao[(b * EE + ks + r) * LL + l0 + q * 4];
            *(float4*)&Bs[r * 36 + q * 4] = b4;
        }
        __syncthreads();
        #pragma unroll
        for (int kk = 0; kk < 16; kk++) {
            float4 a = *(const float4*)&As[kk * 68 + ty * 4];
            ulonglong2 bp = *(const ulonglong2*)&Bs[kk * 36 + tx * 4];
            unsigned long long a0 = pack2(a.x, a.x), a1 = pack2(a.y, a.y);
            unsigned long long a2 = pack2(a.z, a.z), a3 = pack2(a.w, a.w);
            ffma2(accp[0][0], a0, bp.x); ffma2(accp[0][1], a0, bp.y);
            ffma2(accp[1][0], a1, bp.x); ffma2(accp[1][1], a1, bp.y);
            ffma2(accp[2][0], a2, bp.x); ffma2(accp[2][1], a2, bp.y);
            ffma2(accp[3][0], a3, bp.x); ffma2(accp[3][1], a3, bp.y);
        }
        __syncthreads();
    }
    float* X = br ? g_Xv : g_Xh;
    const float* Rb = g_R + (size_t)br * R_SZ;
    #pragma unroll
    for (int i = 0; i < 4; i++) {
        int t = t0 + ty * 4 + i;
        int c = t / NN, r = t - c * NN;
        int base = ((b * NN + r) * CC + c) * LL + l0 + tx * 4;
        float4 res = *(const float4*)&Rb[base];
        float2 p0 = unpack2(accp[i][0]), p1 = unpack2(accp[i][1]);
        float4 o;
        o.x = p0.x + res.x; o.y = p0.y + res.y;
        o.z = p1.x + res.z; o.w = p1.y + res.w;
        *(float4*)&X[base] = o;
    }
}

// ---------------- K6: fused FFN (chunked barriers + FFMA2) ----------------
__global__ void k_ffn(const float* __restrict__ lg0, const float* __restrict__ lb0,
                      const float* __restrict__ pi0, const float* __restrict__ dw0,
                      const float* __restrict__ po0,
                      const float* __restrict__ lg1, const float* __restrict__ lb1,
                      const float* __restrict__ pi1, const float* __restrict__ dw1,
                      const float* __restrict__ po1) {
    int s = blockIdx.x;
    int br = blockIdx.y;
    const float* lg_ = br ? lg1 : lg0;
    const float* lb_ = br ? lb1 : lb0;
    const float* pin_w = br ? pi1 : pi0;
    const float* dw_w = br ? dw1 : dw0;
    const float* pout_w = br ? po1 : po0;
    int l = threadIdx.x;  // 224
    __shared__ __align__(16) float spin[HID2 * 32];
    __shared__ __align__(16) float spoT[HID * 32];
    __shared__ __align__(16) float stA[JCH * LL];
    __shared__ __align__(16) float stG[JCH * LL];
    __shared__ float sdw[HID2 * 9];
    for (int i = l; i < HID2 * 32; i += 224) spin[i] = pin_w[i];
    for (int i = l; i < HID2 * 9; i += 224) sdw[i] = dw_w[i];
    for (int i = l; i < HID * 32; i += 224) {
        int c = i & 31, j = i >> 5;
        spoT[i] = pout_w[c * HID + j];
    }
    float* X = (br ? g_Xv : g_Xh) + s * CC * LL + l;
    float xv[32];
    float mean = 0.f;
    #pragma unroll
    for (int c = 0; c < 32; c++) { xv[c] = X[c * LL]; mean += xv[c]; }
    mean *= (1.0f / 32.0f);
    float var = 0.f;
    #pragma unroll
    for (int c = 0; c < 32; c++) { float d = xv[c] - mean; xv[c] = d; var += d * d; }
    var *= (1.0f / 32.0f);
    float rs = rsqrtf(var + 1e-6f);
    #pragma unroll
    for (int c = 0; c < 32; c++) xv[c] = xv[c] * rs * lg_[c] + lb_[c];
    unsigned long long xp[16];
    #pragma unroll
    for (int q = 0; q < 16; q++) xp[q] = pack2(xv[2 * q], xv[2 * q + 1]);
    __syncthreads();
    unsigned long long accp[16];
    #pragma unroll
    for (int q = 0; q < 16; q++) accp[q] = 0ull;
    int y = l >> 5, x = l & 31;
    for (int jc = 0; jc < HID / JCH; jc++) {
        #pragma unroll
        for (int jj = 0; jj < JCH; jj++) {
            int j = jc * JCH + jj;
            const unsigned long long* w1 = (const unsigned long long*)&spin[j * 32];
            const unsigned long long* w2 = (const unsigned long long*)&spin[(HID + j) * 32];
            unsigned long long aP = 0ull, gP = 0ull;
            #pragma unroll
            for (int q = 0; q < 16; q++) {
                ffma2(aP, w1[q], xp[q]);
                ffma2(gP, w2[q], xp[q]);
            }
            float2 af = unpack2(aP), gf = unpack2(gP);
            stA[jj * LL + l] = af.x + af.y;
            stG[jj * LL + l] = gf.x + gf.y;
        }
        __syncthreads();
        #pragma unroll
        for (int jj = 0; jj < JCH; jj++) {
            int j = jc * JCH + jj;
            float ca = 0.f, cg = 0.f;
            #pragma unroll
            for (int dy = 0; dy < 3; dy++) {
                int yy = y + dy - 1; if (yy < 0 || yy >= 7) continue;
                #pragma unroll
                for (int dx = 0; dx < 3; dx++) {
                    int xx = x + dx - 1; if (xx < 0 || xx >= 32) continue;
                    int li = jj * LL + yy * 32 + xx;
                    ca += stA[li] * sdw[j * 9 + dy * 3 + dx];
                    cg += stG[li] * sdw[(HID + j) * 9 + dy * 3 + dx];
                }
            }
            float gj = gelu_f(ca) * cg;
            unsigned long long gp = pack2(gj, gj);
            const unsigned long long* p4 = (const unsigned long long*)&spoT[j * 32];
            #pragma unroll
            for (int q = 0; q < 16; q++) ffma2(accp[q], gp, p4[q]);
        }
        __syncthreads();
    }
    #pragma unroll
    for (int q = 0; q < 16; q++) {
        float2 p = unpack2(accp[q]);
        X[(2 * q) * LL]     += p.x;
        X[(2 * q + 1) * LL] += p.y;
    }
}

// ---------------- K7: gate ----------------
__global__ void k_gate(const float* __restrict__ f1, const float* __restrict__ f2) {
    int t = blockIdx.x;
    int b = t / 49; int uv = t - b * 49; int u = uv / 7; int v = uv - u * 7;
    int tid = threadIdx.x;  // 256
    int wid = tid >> 5, lane = tid & 31;
    __shared__ float mx[64], sg1[8];
    #pragma unroll
    for (int k = 0; k < 8; k++) {
        int combo = wid * 8 + k;
        int c = combo & 31; bool is2 = combo >= 32;
        float m = -1e30f;
        if (!is2) {
            for (int w = 0; w < 32; w++)
                m = fmaxf(m, g_Xh[((b * NN + v * 32 + w) * CC + c) * LL + u * 32 + lane]);
        } else {
            for (int h = 0; h < 32; h++)
                m = fmaxf(m, g_Xv[((b * NN + u * 32 + h) * CC + c) * LL + v * 32 + lane]);
        }
        #pragma unroll
        for (int o = 16; o > 0; o >>= 1) m = fmaxf(m, __shfl_xor_sync(0xffffffffu, m, o));
        if (lane == 0) mx[combo] = m;
    }
    __syncthreads();
    if (tid < 8) {
        float a = 0.f;
        for (int k = 0; k < 64; k++) a += f1[tid * 64 + k] * mx[k];
        sg1[tid] = (a >= 0.f) ? a : 0.1f * a;
    }
    __syncthreads();
    if (tid < 32) {
        float a = 0.f;
        #pragma unroll
        for (int i = 0; i < 8; i++) a += f2[tid * 8 + i] * sg1[i];
        g_gate[t * 32 + tid] = 1.0f / (1.0f + expf(-a));
    }
}

// ---------------- K8: gated mix ----------------
__global__ void k_final(float* __restrict__ out) {
    int tc = blockIdx.x;
    int t = tc >> 5, c = tc & 31;
    int b = t / 49; int uv = t - b * 49; int u = uv / 7; int v = uv - u * 7;
    __shared__ float sm[32][33];
    int tid = threadIdx.x;
    int lane = tid & 31, row = tid >> 5;
    float g = g_gate[t * 32 + c];
    #pragma unroll
    for (int p = 0; p < 4; p++) {
        int w = row + p * 8;
        sm[w][lane] = g_Xh[((b * NN + v * 32 + w) * CC + c) * LL + u * 32 + lane];
    }
    __syncthreads();
    #pragma unroll
    for (int p = 0; p < 4; p++) {
        int h = row + p * 8;
        float o2 = g_Xv[((b * NN + u * 32 + h) * CC + c) * LL + v * 32 + lane];
        out[((t * CC + c) * 32 + h) * 32 + lane] = sm[lane][h] * g + o2 * (1.0f - g);
    }
}

// ---------------- launch ----------------
extern "C" void kernel_launch(void* const* d_in, const int* in_sizes, int n_in,
                              void* d_out, int out_size) {
    (void)in_sizes; (void)n_in; (void)out_size;
    const float* xlf = (const float*)d_in[0];
    const float* f1  = (const float*)d_in[27];
    const float* f2  = (const float*)d_in[28];
    // branch 0 (h_) at offset 1, branch 1 (v_) at offset 14
    const float* lw0 = (const float*)d_in[1];  const float* lw1 = (const float*)d_in[14];
    const float* tp0 = (const float*)d_in[2];  const float* tp1 = (const float*)d_in[15];
    const float* g0  = (const float*)d_in[3];  const float* g1  = (const float*)d_in[16];
    const float* b0  = (const float*)d_in[4];  const float* b1  = (const float*)d_in[17];
    const float* qw0 = (const float*)d_in[5];  const float* qw1 = (const float*)d_in[18];
    const float* dq0 = (const float*)d_in[6];  const float* dq1 = (const float*)d_in[19];
    const float* pw0 = (const float*)d_in[7];  const float* pw1 = (const float*)d_in[20];
    const float* ac0 = (const float*)d_in[8];  const float* ac1 = (const float*)d_in[21];
    const float* eg0 = (const float*)d_in[9];  const float* eg1 = (const float*)d_in[22];
    const float* eb0 = (const float*)d_in[10]; const float* eb1 = (const float*)d_in[23];
    const float* pi0 = (const float*)d_in[11]; const float* pi1 = (const float*)d_in[24];
    const float* dw0 = (const float*)d_in[12]; const float* dw1 = (const float*)d_in[25];
    const float* po0 = (const float*)d_in[13]; const float* po1 = (const float*)d_in[26];

    k_pack  <<<6272, 256>>>(xlf);
    k_lin   <<<dim3(2, 14, KSPLIT * 2), 256>>>(lw0, lw1);
    k_ln_qkv<<<dim3(896, 2), 128>>>(g0, b0, qw0, g1, b1, qw1);
    k_dw3   <<<dim3((BBATCH * 384 * LL) / 256, 2), 256>>>(dq0, dq1);
    k_norm  <<<dim3(896, 2), 128>>>();
    k_attn  <<<dim3(56, 4, 2), 256>>>(tp0, ac0, tp1, ac1);
    k_proj  <<<dim3(112, 7, 8), 128>>>(pw0, pw1);
    k_ffn   <<<dim3(896, 2), 224>>>(eg0, eb0, pi0, dw0, po0, eg1, eb1, pi1, dw1, po1);
    k_gate  <<<196, 256>>>(f1, f2);
    k_final <<<OUTELEMS / 1024, 256>>>((float*)d_out);
}

// round 17
// speedup vs baseline: 2.4824x; 1.0236x over previous
#include <cuda_runtime.h>
#include <math.h>

#define ANG 7
#define CC 32
#define EE 128
#define NHEADS 4
#define NN 224
#define LL 224
#define TOKD 7168
#define HID 85
#define HID2 170
#define BBATCH 4
#define SAMP 896
#define KSPLIT 16
#define KCH 448          // TOKD / KSPLIT
#define OUTELEMS 6422528
#define JCH 5            // ffn chunk (85 = 17*5)

// per-branch sizes
#define AT_SZ (SAMP * TOKD)
#define R_SZ  (SAMP * CC * LL)
#define XP_SZ (KSPLIT * SAMP * EE)
#define QP_SZ (BBATCH * 3 * EE * LL)
#define QN_SZ (BBATCH * NHEADS * LL * 32)
#define AO_SZ (BBATCH * EE * LL)

// ---------------- scratch (16B-aligned; [branch] major) ----------------
__device__ __align__(16) float g_At[2 * AT_SZ];
__device__ __align__(16) float g_R[2 * R_SZ];
__device__ __align__(16) float g_xpart[2 * XP_SZ];
__device__ __align__(16) float g_qkvpre[2 * QP_SZ];
__device__ __align__(16) float g_qkv[2 * QP_SZ];
__device__ __align__(16) float g_qn[2 * QN_SZ];
__device__ __align__(16) float g_kn[2 * QN_SZ];
__device__ __align__(16) float g_vvT[2 * QN_SZ];   // transposed: [bh*32+d][l]
__device__ __align__(16) float g_ao[2 * AO_SZ];
__device__ __align__(16) float g_Xh[R_SZ];
__device__ __align__(16) float g_Xv[R_SZ];
__device__ __align__(16) float g_gate[196 * CC];

__device__ __forceinline__ float gelu_f(float x) {
    return 0.5f * x * (1.0f + erff(x * 0.70710678118654752440f));
}

// ---- packed f32x2 helpers ----
__device__ __forceinline__ void ffma2(unsigned long long& d, unsigned long long a, unsigned long long b) {
    asm("fma.rn.f32x2 %0, %1, %2, %0;" : "+l"(d) : "l"(a), "l"(b));
}
__device__ __forceinline__ unsigned long long pack2(float lo, float hi) {
    unsigned long long r;
    asm("mov.b64 %0, {%1, %2};" : "=l"(r) : "r"(__float_as_uint(lo)), "r"(__float_as_uint(hi)));
    return r;
}
__device__ __forceinline__ float2 unpack2(unsigned long long v) {
    unsigned int a, b;
    asm("mov.b64 {%0, %1}, %2;" : "=r"(a), "=r"(b) : "l"(v));
    return make_float2(__uint_as_float(a), __uint_as_float(b));
}

// ---------------- K0: merged pack (one read, 4 writes) ----------------
__global__ void k_pack(const float* __restrict__ xlf) {
    int bid = blockIdx.x;
    int c = bid & 31; int t = bid >> 5;
    int b = t / 49; int uv = t - b * 49; int u = uv / 7; int v = uv - u * 7;
    __shared__ float sm[32][33];
    int tid = threadIdx.x;
    int lane = tid & 31, row = tid >> 5;
    const float* src = xlf + ((size_t)t * 32 + c) * 1024;
    #pragma unroll
    for (int p = 0; p < 4; p++) {
        int h = row + p * 8;
        sm[h][lane] = src[h * 32 + lane];
    }
    __syncthreads();
    #pragma unroll
    for (int p = 0; p < 4; p++) {
        int h = row + p * 8;
        g_At[(b * 224 + u * 32 + h) * TOKD + c * 224 + v * 32 + lane] = sm[h][lane];
        g_R[((b * NN + v * 32 + h) * CC + c) * LL + u * 32 + lane] = sm[lane][h];
        g_At[AT_SZ + (b * 224 + v * 32 + h) * TOKD + c * 224 + u * 32 + lane] = sm[lane][h];
        g_R[R_SZ + ((b * NN + u * 32 + h) * CC + c) * LL + v * 32 + lane] = sm[h][lane];
    }
}

// ---------------- K1: lin GEMM, split-K, ping-pong double-buffer ----------------
__global__ void k_lin(const float* __restrict__ lin_w0, const float* __restrict__ lin_w1) {
    __shared__ __align__(16) float As[2][16 * 68];
    __shared__ __align__(16) float Bs[2][16 * 68];
    int tid = threadIdx.x;
    int tx = tid & 15, ty = tid >> 4;
    int e0 = blockIdx.x * 64, m0 = blockIdx.y * 64;
    int kb = blockIdx.z & 15, br = blockIdx.z >> 4;
    const float* lw = br ? lin_w1 : lin_w0;
    const float* At = g_At + (size_t)br * AT_SZ;
    int kbase = kb * KCH;
    unsigned long long accp[4][2];
    #pragma unroll
    for (int i = 0; i < 4; i++) { accp[i][0] = 0ull; accp[i][1] = 0ull; }
    int r = tid >> 2, q = tid & 3;
    const float* aptr = &At[(m0 + r) * TOKD + kbase + q * 4];
    const float* bptr = &lw[(e0 + r) * TOKD + kbase + q * 4];
    {
        float4 av = *(const float4*)aptr;
        float4 bv = *(const float4*)bptr;
        As[0][(q * 4 + 0) * 68 + r] = av.x; As[0][(q * 4 + 1) * 68 + r] = av.y;
        As[0][(q * 4 + 2) * 68 + r] = av.z; As[0][(q * 4 + 3) * 68 + r] = av.w;
        Bs[0][(q * 4 + 0) * 68 + r] = bv.x; Bs[0][(q * 4 + 1) * 68 + r] = bv.y;
        Bs[0][(q * 4 + 2) * 68 + r] = bv.z; Bs[0][(q * 4 + 3) * 68 + r] = bv.w;
    }
    __syncthreads();
    int p = 0;
    for (int ks = 16; ks < KCH; ks += 16) {
        float4 av = *(const float4*)(aptr + ks);
        float4 bv = *(const float4*)(bptr + ks);
        #pragma unroll
        for (int kk = 0; kk < 16; kk++) {
            float4 a = *(const float4*)&As[p][kk * 68 + ty * 4];
            ulonglong2 bp = *(const ulonglong2*)&Bs[p][kk * 68 + tx * 4];
            unsigned long long a0 = pack2(a.x, a.x), a1 = pack2(a.y, a.y);
            unsigned long long a2 = pack2(a.z, a.z), a3 = pack2(a.w, a.w);
            ffma2(accp[0][0], a0, bp.x); ffma2(accp[0][1], a0, bp.y);
            ffma2(accp[1][0], a1, bp.x); ffma2(accp[1][1], a1, bp.y);
            ffma2(accp[2][0], a2, bp.x); ffma2(accp[2][1], a2, bp.y);
            ffma2(accp[3][0], a3, bp.x); ffma2(accp[3][1], a3, bp.y);
        }
        int np = 1 - p;
        As[np][(q * 4 + 0) * 68 + r] = av.x; As[np][(q * 4 + 1) * 68 + r] = av.y;
        As[np][(q * 4 + 2) * 68 + r] = av.z; As[np][(q * 4 + 3) * 68 + r] = av.w;
        Bs[np][(q * 4 + 0) * 68 + r] = bv.x; Bs[np][(q * 4 + 1) * 68 + r] = bv.y;
        Bs[np][(q * 4 + 2) * 68 + r] = bv.z; Bs[np][(q * 4 + 3) * 68 + r] = bv.w;
        __syncthreads();
        p = np;
    }
    #pragma unroll
    for (int kk = 0; kk < 16; kk++) {
        float4 a = *(const float4*)&As[p][kk * 68 + ty * 4];
        ulonglong2 bp = *(const ulonglong2*)&Bs[p][kk * 68 + tx * 4];
        unsigned long long a0 = pack2(a.x, a.x), a1 = pack2(a.y, a.y);
        unsigned long long a2 = pack2(a.z, a.z), a3 = pack2(a.w, a.w);
        ffma2(accp[0][0], a0, bp.x); ffma2(accp[0][1], a0, bp.y);
        ffma2(accp[1][0], a1, bp.x); ffma2(accp[1][1], a1, bp.y);
        ffma2(accp[2][0], a2, bp.x); ffma2(accp[2][1], a2, bp.y);
        ffma2(accp[3][0], a3, bp.x); ffma2(accp[3][1], a3, bp.y);
    }
    float* xp = g_xpart + (size_t)br * XP_SZ;
    #pragma unroll
    for (int i = 0; i < 4; i++) {
        int m = m0 + ty * 4 + i;
        float2 p0 = unpack2(accp[i][0]), p1 = unpack2(accp[i][1]);
        float4 st4 = make_float4(p0.x, p0.y, p1.x, p1.y);
        *(float4*)&xp[(kb * SAMP + m) * EE + e0 + tx * 4] = st4;
    }
}

// ---------------- K2: reduce partials + LN(E) + qkv 1x1 (4 tokens/block) ----------------
__global__ void k_ln_qkv(const float* __restrict__ gw0, const float* __restrict__ bw0,
                         const float* __restrict__ qw0,
                         const float* __restrict__ gw1, const float* __restrict__ bw1,
                         const float* __restrict__ qw1) {
    int xb = blockIdx.x;            // 224 per branch: b = xb/56, l0 = (xb%56)*4
    int br = blockIdx.y;
    int b = xb / 56; int l0 = (xb - b * 56) * 4;
    const float* gw = br ? gw1 : gw0;
    const float* bw = br ? bw1 : bw0;
    const float* qkv_w = br ? qw1 : qw0;
    const float* xp = g_xpart + (size_t)br * XP_SZ;
    int tid = threadIdx.x;          // 128
    int w = tid >> 5, lane = tid & 31;
    __shared__ __align__(16) float nvT[128 * 4];   // [c][t]
    // phase 1: warp w owns token l0+w
    {
        int p = b * LL + l0 + w;
        float vch[4];
        #pragma unroll
        for (int q = 0; q < 4; q++) {
            int ch = lane + 32 * q;
            float acc = 0.f;
            #pragma unroll
            for (int kb = 0; kb < KSPLIT; kb++) acc += xp[(kb * SAMP + p) * EE + ch];
            vch[q] = acc;
        }
        float sum = vch[0] + vch[1] + vch[2] + vch[3];
        #pragma unroll
        for (int o = 16; o > 0; o >>= 1) sum += __shfl_xor_sync(0xffffffffu, sum, o);
        float mean = sum * (1.0f / 128.0f);
        float var = 0.f;
        #pragma unroll
        for (int q = 0; q < 4; q++) { float d = vch[q] - mean; vch[q] = d; var += d * d; }
        #pragma unroll
        for (int o = 16; o > 0; o >>= 1) var += __shfl_xor_sync(0xffffffffu, var, o);
        float rs = rsqrtf(var * (1.0f / 128.0f) + 1e-6f);
        #pragma unroll
        for (int q = 0; q < 4; q++) {
            int ch = lane + 32 * q;
            nvT[ch * 4 + w] = vch[q] * rs * gw[ch] + bw[ch];
        }
    }
    __syncthreads();
    // phase 2: each thread computes weight rows against all 4 tokens
    float* outp = g_qkvpre + (size_t)br * QP_SZ;
    #pragma unroll
    for (int jj = 0; jj < 3; jj++) {
        int j = tid + jj * 128;
        const float4* wr = reinterpret_cast<const float4*>(qkv_w + j * EE);
        float4 a = make_float4(0.f, 0.f, 0.f, 0.f);
        #pragma unroll
        for (int c4 = 0; c4 < 32; c4++) {
            float4 wv = wr[c4];
            float4 n0 = *(const float4*)&nvT[(c4 * 4 + 0) * 4];
            float4 n1 = *(const float4*)&nvT[(c4 * 4 + 1) * 4];
            float4 n2 = *(const float4*)&nvT[(c4 * 4 + 2) * 4];
            float4 n3 = *(const float4*)&nvT[(c4 * 4 + 3) * 4];
            a.x += wv.x * n0.x + wv.y * n1.x + wv.z * n2.x + wv.w * n3.x;
            a.y += wv.x * n0.y + wv.y * n1.y + wv.z * n2.y + wv.w * n3.y;
            a.z += wv.x * n0.z + wv.y * n1.z + wv.z * n2.z + wv.w * n3.z;
            a.w += wv.x * n0.w + wv.y * n1.w + wv.z * n2.w + wv.w * n3.w;
        }
        *(float4*)&outp[(b * 384 + j) * LL + l0] = a;
    }
}

// ---------------- K3: depthwise 3x3 ----------------
__global__ void k_dw3(const float* __restrict__ w0, const float* __restrict__ w1) {
    int i = blockIdx.x * blockDim.x + threadIdx.x;
    int br = blockIdx.y;
    const float* w = br ? w1 : w0;
    int l = i % LL; int ch = (i / LL) % 384; int b = i / (LL * 384);
    int y = l >> 5, x = l & 31;
    const float* src = g_qkvpre + (size_t)br * QP_SZ + (b * 384 + ch) * LL;
    float acc = 0.f;
    #pragma unroll
    for (int dy = 0; dy < 3; dy++) {
        int yy = y + dy - 1; if (yy < 0 || yy >= 7) continue;
        #pragma unroll
        for (int dx = 0; dx < 3; dx++) {
            int xx = x + dx - 1; if (xx < 0 || xx >= 32) continue;
            acc += src[yy * 32 + xx] * w[ch * 9 + dy * 3 + dx];
        }
    }
    g_qkv[(size_t)br * QP_SZ + i] = acc;
}

// ---------------- K4a: l2-normalize q,k; V transposed ----------------
__global__ void k_norm() {
    int row = blockIdx.x * 4 + (threadIdx.x >> 5);
    int br = blockIdx.y;
    int dd = threadIdx.x & 31;
    int l = row % LL; int bh = row / LL; int h = bh & 3; int b = bh >> 2;
    int base = (b * 384 + h * 32 + dd) * LL + l;
    const float* qk = g_qkv + (size_t)br * QP_SZ;
    float qv = qk[base];
    float kv = qk[base + 128 * LL];
    float vv = qk[base + 256 * LL];
    float sq = qv * qv, sk = kv * kv;
    #pragma unroll
    for (int o = 16; o > 0; o >>= 1) {
        sq += __shfl_xor_sync(0xffffffffu, sq, o);
        sk += __shfl_xor_sync(0xffffffffu, sk, o);
    }
    float dq = fmaxf(sqrtf(sq), 1e-12f), dk = fmaxf(sqrtf(sk), 1e-12f);
    size_t o2 = (size_t)br * QN_SZ;
    g_qn[o2 + row * 32 + dd] = qv / dq;
    g_kn[o2 + row * 32 + dd] = kv / dk;
    g_vvT[o2 + (bh * 32 + dd) * LL + l] = vv;   // transposed layout
}

// ---------------- K4b: attention, 4 tokens per block (contiguous AV) ----------------
__global__ void k_attn(const float* __restrict__ temp0, const float* __restrict__ attca0,
                       const float* __restrict__ temp1, const float* __restrict__ attca1) {
    int tg0 = blockIdx.x * 4;
    int b = blockIdx.y;
    int br = blockIdx.z;
    const float* temp = br ? temp1 : temp0;
    const float* attca = br ? attca1 : attca0;
    const float* qn = g_qn + (size_t)br * QN_SZ;
    const float* kn = g_kn + (size_t)br * QN_SZ;
    const float* vvb = g_vvT + (size_t)br * QN_SZ;
    int tid = threadIdx.x;  // 256
    __shared__ __align__(16) float sq[4 * 128];
    __shared__ __align__(16) float sat[16 * 224];
    __shared__ __align__(16) float outp[256 * 4];
    __shared__ float wred[8 * 16];
    __shared__ float gred[16];
    __shared__ float sca[32];
    if (tid < 32) sca[tid] = attca[tid];
    for (int i = tid; i < 512; i += 256) {
        int t = i >> 7, hd = i & 127;
        sq[i] = qn[((b * 4 + (hd >> 5)) * LL + tg0 + t) * 32 + (hd & 31)];
    }
    __syncthreads();

    int m = tid; bool act = (m < LL);
    float lg[16];
    if (act) {
        #pragma unroll
        for (int h = 0; h < 4; h++) {
            const float4* kr = (const float4*)&kn[((b * 4 + h) * LL + m) * 32];
            float s[4] = {0.f, 0.f, 0.f, 0.f};
            #pragma unroll
            for (int q = 0; q < 8; q++) {
                float4 kv = kr[q];
                #pragma unroll
                for (int t = 0; t < 4; t++) {
                    float4 qv = *(const float4*)&sq[t * 128 + h * 32 + q * 4];
                    s[t] += kv.x * qv.x + kv.y * qv.y + kv.z * qv.z + kv.w * qv.w;
                }
            }
            float tp = temp[h];
            #pragma unroll
            for (int t = 0; t < 4; t++) lg[h * 4 + t] = s[t] * tp;
        }
    } else {
        #pragma unroll
        for (int i = 0; i < 16; i++) lg[i] = -1e30f;
    }
    int wid = tid >> 5, lane = tid & 31;
    float red[16];
    #pragma unroll
    for (int i = 0; i < 16; i++) red[i] = lg[i];
    #pragma unroll
    for (int o = 16; o > 0; o >>= 1) {
        #pragma unroll
        for (int i = 0; i < 16; i++) red[i] = fmaxf(red[i], __shfl_xor_sync(0xffffffffu, red[i], o));
    }
    if (lane == 0) {
        #pragma unroll
        for (int i = 0; i < 16; i++) wred[wid * 16 + i] = red[i];
    }
    __syncthreads();
    if (tid < 16) {
        float vmx = wred[tid];
        #pragma unroll
        for (int w = 1; w < 8; w++) vmx = fmaxf(vmx, wred[w * 16 + tid]);
        gred[tid] = vmx;
    }
    __syncthreads();
    float e[16];
    #pragma unroll
    for (int i = 0; i < 16; i++) e[i] = act ? expf(lg[i] - gred[i]) : 0.f;
    __syncthreads();
    #pragma unroll
    for (int i = 0; i < 16; i++) red[i] = e[i];
    #pragma unroll
    for (int o = 16; o > 0; o >>= 1) {
        #pragma unroll
        for (int i = 0; i < 16; i++) red[i] += __shfl_xor_sync(0xffffffffu, red[i], o);
    }
    if (lane == 0) {
        #pragma unroll
        for (int i = 0; i < 16; i++) wred[wid * 16 + i] = red[i];
    }
    __syncthreads();
    if (tid < 16) {
        float vs = wred[tid];
        #pragma unroll
        for (int w = 1; w < 8; w++) vs += wred[w * 16 + tid];
        gred[tid] = vs;
    }
    __syncthreads();
    if (act) {
        float ag[16];
        #pragma unroll
        for (int i = 0; i < 16; i++) { float a = fmaxf(lg[i], 0.f); a *= a; ag[i] = gelu_f(a) * a; }
        #pragma unroll
        for (int t = 0; t < 4; t++) {
            #pragma unroll
            for (int h = 0; h < 4; h++) {
                float sc = sca[h * 4 + 0] * ag[0 * 4 + t] + sca[h * 4 + 1] * ag[1 * 4 + t] +
                           sca[h * 4 + 2] * ag[2 * 4 + t] + sca[h * 4 + 3] * ag[3 * 4 + t];
                float sh = sca[(4 + h) * 4 + 0] * ag[0 * 4 + t] + sca[(4 + h) * 4 + 1] * ag[1 * 4 + t] +
                           sca[(4 + h) * 4 + 2] * ag[2 * 4 + t] + sca[(4 + h) * 4 + 3] * ag[3 * 4 + t];
                float p = e[h * 4 + t] / gred[h * 4 + t];
                sat[(t * 4 + h) * 224 + m] = p * (1.0f + sc) + sh;
            }
        }
    }
    __syncthreads();
    {
        int half = tid >> 7, hd = tid & 127, h = hd >> 5, dd = hd & 31;
        float o[4] = {0.f, 0.f, 0.f, 0.f};
        const float* vb = &vvb[((b * 4 + h) * 32 + dd) * LL];   // contiguous over mm
        int mmend = half * 112 + 112;
        for (int mm = half * 112; mm < mmend; mm++) {
            float v = vb[mm];
            #pragma unroll
            for (int t = 0; t < 4; t++) o[t] += sat[(t * 4 + h) * 224 + mm] * v;
        }
        #pragma unroll
        for (int t = 0; t < 4; t++) outp[tid * 4 + t] = o[t];
    }
    __syncthreads();
    if (tid < 128) {
        float4 r4;
        r4.x = outp[tid * 4 + 0] + outp[(tid + 128) * 4 + 0];
        r4.y = outp[tid * 4 + 1] + outp[(tid + 128) * 4 + 1];
        r4.z = outp[tid * 4 + 2] + outp[(tid + 128) * 4 + 2];
        r4.w = outp[tid * 4 + 3] + outp[(tid + 128) * 4 + 3];
        *(float4*)&g_ao[(size_t)br * AO_SZ + (b * EE + tid) * LL + tg0] = r4;
    }
}

// ---------------- K5: proj GEMM + residual ----------------
__global__ void k_proj(const float* __restrict__ pw0, const float* __restrict__ pw1) {
    __shared__ __align__(16) float As[16 * 68];
    __shared__ __align__(16) float Bs[16 * 36];
    int tid = threadIdx.x;
    int tx = tid & 7, ty = tid >> 3;
    int t0 = blockIdx.x * 64, l0 = blockIdx.y * 32;
    int b = blockIdx.z & 3, br = blockIdx.z >> 2;
    const float* proj_w = br ? pw1 : pw0;
    const float* ao = g_ao + (size_t)br * AO_SZ;
    unsigned long long accp[4][2];
    #pragma unroll
    for (int i = 0; i < 4; i++) { accp[i][0] = 0ull; accp[i][1] = 0ull; }
    for (int ks = 0; ks < EE; ks += 16) {
        #pragma unroll
        for (int ii = 0; ii < 2; ii++) {
            int idx = tid * 2 + ii;
            int r = idx >> 2, q = idx & 3;
            float4 a4 = *(const float4*)&proj_w[(t0 + r) * EE + ks + q * 4];
            As[(q * 4 + 0) * 68 + r] = a4.x; As[(q * 4 + 1) * 68 + r] = a4.y;
            As[(q * 4 + 2) * 68 + r] = a4.z; As[(q * 4 + 3) * 68 + r] = a4.w;
        }
        {
            int r = tid >> 3, q = tid & 7;
            float4 b4 = *(const float4*)&ao[(b * EE + ks + r) * LL + l0 + q * 4];
            *(float4*)&Bs[r * 36 + q * 4] = b4;
        }
        __syncthreads();
        #pragma unroll
        for (int kk = 0; kk < 16; kk++) {
            float4 a = *(const float4*)&As[kk * 68 + ty * 4];
            ulonglong2 bp = *(const ulonglong2*)&Bs[kk * 36 + tx * 4];
            unsigned long long a0 = pack2(a.x, a.x), a1 = pack2(a.y, a.y);
            unsigned long long a2 = pack2(a.z, a.z), a3 = pack2(a.w, a.w);
            ffma2(accp[0][0], a0, bp.x); ffma2(accp[0][1], a0, bp.y);
            ffma2(accp[1][0], a1, bp.x); ffma2(accp[1][1], a1, bp.y);
            ffma2(accp[2][0], a2, bp.x); ffma2(accp[2][1], a2, bp.y);
            ffma2(accp[3][0], a3, bp.x); ffma2(accp[3][1], a3, bp.y);
        }
        __syncthreads();
    }
    float* X = br ? g_Xv : g_Xh;
    const float* Rb = g_R + (size_t)br * R_SZ;
    #pragma unroll
    for (int i = 0; i < 4; i++) {
        int t = t0 + ty * 4 + i;
        int c = t / NN, r = t - c * NN;
        int base = ((b * NN + r) * CC + c) * LL + l0 + tx * 4;
        float4 res = *(const float4*)&Rb[base];
        float2 p0 = unpack2(accp[i][0]), p1 = unpack2(accp[i][1]);
        float4 o;
        o.x = p0.x + res.x; o.y = p0.y + res.y;
        o.z = p1.x + res.z; o.w = p1.y + res.w;
        *(float4*)&X[base] = o;
    }
}

// ---------------- K6: fused FFN (chunked barriers + FFMA2) ----------------
__global__ void k_ffn(const float* __restrict__ lg0, const float* __restrict__ lb0,
                      const float* __restrict__ pi0, const float* __restrict__ dw0,
                      const float* __restrict__ po0,
                      const float* __restrict__ lg1, const float* __restrict__ lb1,
                      const float* __restrict__ pi1, const float* __restrict__ dw1,
                      const float* __restrict__ po1) {
    int s = blockIdx.x;
    int br = blockIdx.y;
    const float* lg_ = br ? lg1 : lg0;
    const float* lb_ = br ? lb1 : lb0;
    const float* pin_w = br ? pi1 : pi0;
    const float* dw_w = br ? dw1 : dw0;
    const float* pout_w = br ? po1 : po0;
    int l = threadIdx.x;  // 224
    __shared__ __align__(16) float spin[HID2 * 32];
    __shared__ __align__(16) float spoT[HID * 32];
    __shared__ __align__(16) float stA[JCH * LL];
    __shared__ __align__(16) float stG[JCH * LL];
    __shared__ float sdw[HID2 * 9];
    for (int i = l; i < HID2 * 32; i += 224) spin[i] = pin_w[i];
    for (int i = l; i < HID2 * 9; i += 224) sdw[i] = dw_w[i];
    for (int i = l; i < HID * 32; i += 224) {
        int c = i & 31, j = i >> 5;
        spoT[i] = pout_w[c * HID + j];
    }
    float* X = (br ? g_Xv : g_Xh) + s * CC * LL + l;
    float xv[32];
    float mean = 0.f;
    #pragma unroll
    for (int c = 0; c < 32; c++) { xv[c] = X[c * LL]; mean += xv[c]; }
    mean *= (1.0f / 32.0f);
    float var = 0.f;
    #pragma unroll
    for (int c = 0; c < 32; c++) { float d = xv[c] - mean; xv[c] = d; var += d * d; }
    var *= (1.0f / 32.0f);
    float rs = rsqrtf(var + 1e-6f);
    #pragma unroll
    for (int c = 0; c < 32; c++) xv[c] = xv[c] * rs * lg_[c] + lb_[c];
    unsigned long long xp[16];
    #pragma unroll
    for (int q = 0; q < 16; q++) xp[q] = pack2(xv[2 * q], xv[2 * q + 1]);
    __syncthreads();
    unsigned long long accp[16];
    #pragma unroll
    for (int q = 0; q < 16; q++) accp[q] = 0ull;
    int y = l >> 5, x = l & 31;
    for (int jc = 0; jc < HID / JCH; jc++) {
        #pragma unroll
        for (int jj = 0; jj < JCH; jj++) {
            int j = jc * JCH + jj;
            const unsigned long long* w1 = (const unsigned long long*)&spin[j * 32];
            const unsigned long long* w2 = (const unsigned long long*)&spin[(HID + j) * 32];
            unsigned long long aP = 0ull, gP = 0ull;
            #pragma unroll
            for (int q = 0; q < 16; q++) {
                ffma2(aP, w1[q], xp[q]);
                ffma2(gP, w2[q], xp[q]);
            }
            float2 af = unpack2(aP), gf = unpack2(gP);
            stA[jj * LL + l] = af.x + af.y;
            stG[jj * LL + l] = gf.x + gf.y;
        }
        __syncthreads();
        #pragma unroll
        for (int jj = 0; jj < JCH; jj++) {
            int j = jc * JCH + jj;
            float ca = 0.f, cg = 0.f;
            #pragma unroll
            for (int dy = 0; dy < 3; dy++) {
                int yy = y + dy - 1; if (yy < 0 || yy >= 7) continue;
                #pragma unroll
                for (int dx = 0; dx < 3; dx++) {
                    int xx = x + dx - 1; if (xx < 0 || xx >= 32) continue;
                    int li = jj * LL + yy * 32 + xx;
                    ca += stA[li] * sdw[j * 9 + dy * 3 + dx];
                    cg += stG[li] * sdw[(HID + j) * 9 + dy * 3 + dx];
                }
            }
            float gj = gelu_f(ca) * cg;
            unsigned long long gp = pack2(gj, gj);
            const unsigned long long* p4 = (const unsigned long long*)&spoT[j * 32];
            #pragma unroll
            for (int q = 0; q < 16; q++) ffma2(accp[q], gp, p4[q]);
        }
        __syncthreads();
    }
    #pragma unroll
    for (int q = 0; q < 16; q++) {
        float2 p = unpack2(accp[q]);
        X[(2 * q) * LL]     += p.x;
        X[(2 * q + 1) * LL] += p.y;
    }
}

// ---------------- K7: gate ----------------
__global__ void k_gate(const float* __restrict__ f1, const float* __restrict__ f2) {
    int t = blockIdx.x;
    int b = t / 49; int uv = t - b * 49; int u = uv / 7; int v = uv - u * 7;
    int tid = threadIdx.x;  // 256
    int wid = tid >> 5, lane = tid & 31;
    __shared__ float mx[64], sg1[8];
    #pragma unroll
    for (int k = 0; k < 8; k++) {
        int combo = wid * 8 + k;
        int c = combo & 31; bool is2 = combo >= 32;
        float m = -1e30f;
        if (!is2) {
            for (int w = 0; w < 32; w++)
                m = fmaxf(m, g_Xh[((b * NN + v * 32 + w) * CC + c) * LL + u * 32 + lane]);
        } else {
            for (int h = 0; h < 32; h++)
                m = fmaxf(m, g_Xv[((b * NN + u * 32 + h) * CC + c) * LL + v * 32 + lane]);
        }
        #pragma unroll
        for (int o = 16; o > 0; o >>= 1) m = fmaxf(m, __shfl_xor_sync(0xffffffffu, m, o));
        if (lane == 0) mx[combo] = m;
    }
    __syncthreads();
    if (tid < 8) {
        float a = 0.f;
        for (int k = 0; k < 64; k++) a += f1[tid * 64 + k] * mx[k];
        sg1[tid] = (a >= 0.f) ? a : 0.1f * a;
    }
    __syncthreads();
    if (tid < 32) {
        float a = 0.f;
        #pragma unroll
        for (int i = 0; i < 8; i++) a += f2[tid * 8 + i] * sg1[i];
        g_gate[t * 32 + tid] = 1.0f / (1.0f + expf(-a));
    }
}

// ---------------- K8: gated mix ----------------
__global__ void k_final(float* __restrict__ out) {
    int tc = blockIdx.x;
    int t = tc >> 5, c = tc & 31;
    int b = t / 49; int uv = t - b * 49; int u = uv / 7; int v = uv - u * 7;
    __shared__ float sm[32][33];
    int tid = threadIdx.x;
    int lane = tid & 31, row = tid >> 5;
    float g = g_gate[t * 32 + c];
    #pragma unroll
    for (int p = 0; p < 4; p++) {
        int w = row + p * 8;
        sm[w][lane] = g_Xh[((b * NN + v * 32 + w) * CC + c) * LL + u * 32 + lane];
    }
    __syncthreads();
    #pragma unroll
    for (int p = 0; p < 4; p++) {
        int h = row + p * 8;
        float o2 = g_Xv[((b * NN + u * 32 + h) * CC + c) * LL + v * 32 + lane];
        out[((t * CC + c) * 32 + h) * 32 + lane] = sm[lane][h] * g + o2 * (1.0f - g);
    }
}

// ---------------- launch ----------------
extern "C" void kernel_launch(void* const* d_in, const int* in_sizes, int n_in,
                              void* d_out, int out_size) {
    (void)in_sizes; (void)n_in; (void)out_size;
    const float* xlf = (const float*)d_in[0];
    const float* f1  = (const float*)d_in[27];
    const float* f2  = (const float*)d_in[28];
    const float* lw0 = (const float*)d_in[1];  const float* lw1 = (const float*)d_in[14];
    const float* tp0 = (const float*)d_in[2];  const float* tp1 = (const float*)d_in[15];
    const float* g0  = (const float*)d_in[3];  const float* g1  = (const float*)d_in[16];
    const float* b0  = (const float*)d_in[4];  const float* b1  = (const float*)d_in[17];
    const float* qw0 = (const float*)d_in[5];  const float* qw1 = (const float*)d_in[18];
    const float* dq0 = (const float*)d_in[6];  const float* dq1 = (const float*)d_in[19];
    const float* pw0 = (const float*)d_in[7];  const float* pw1 = (const float*)d_in[20];
    const float* ac0 = (const float*)d_in[8];  const float* ac1 = (const float*)d_in[21];
    const float* eg0 = (const float*)d_in[9];  const float* eg1 = (const float*)d_in[22];
    const float* eb0 = (const float*)d_in[10]; const float* eb1 = (const float*)d_in[23];
    const float* pi0 = (const float*)d_in[11]; const float* pi1 = (const float*)d_in[24];
    const float* dw0 = (const float*)d_in[12]; const float* dw1 = (const float*)d_in[25];
    const float* po0 = (const float*)d_in[13]; const float* po1 = (const float*)d_in[26];

    k_pack  <<<6272, 256>>>(xlf);
    k_lin   <<<dim3(2, 14, KSPLIT * 2), 256>>>(lw0, lw1);
    k_ln_qkv<<<dim3(224, 2), 128>>>(g0, b0, qw0, g1, b1, qw1);
    k_dw3   <<<dim3((BBATCH * 384 * LL) / 256, 2), 256>>>(dq0, dq1);
    k_norm  <<<dim3(896, 2), 128>>>();
    k_attn  <<<dim3(56, 4, 2), 256>>>(tp0, ac0, tp1, ac1);
    k_proj  <<<dim3(112, 7, 8), 128>>>(pw0, pw1);
    k_ffn   <<<dim3(896, 2), 224>>>(eg0, eb0, pi0, dw0, po0, eg1, eb1, pi1, dw1, po1);
    k_gate  <<<196, 256>>>(f1, f2);
    k_final <<<OUTELEMS / 1024, 256>>>((float*)d_out);
}